// round 11
// baseline (speedup 1.0000x reference)
#include <cuda_runtime.h>
#include <cuda_fp16.h>
#include <cstdint>

#define NNI 32
#define HW  4096

// ---------------- scratch ----------------
__device__ __align__(128) __half g_spk[(size_t)NNI * HW * 256];   // spikes NHWC fp16
__device__ __align__(128) float  g_y  [(size_t)NNI * HW * 192];   // conv1 out NHWC f32
__device__ __align__(128) __half g_ybh[(size_t)NNI * HW * 256];   // BN out fp16 (4x64 padded)
__device__ __align__(128) __half g_wb1[36 * 192 * 64];            // [tap*4+chunk][192][64] swizzled
__device__ __align__(128) __half g_wb2[36 * 80 * 64];             // [tap*4+g][80][64] sign, swizzled
__device__ float g_p1[1024 * 192], g_p2[1024 * 192];              // per-conv1-CTA BN partials
__device__ float g_scale[192], g_shift[192];

// ---------------- PTX helpers (sm_80-compatible only) ----------------
__device__ __forceinline__ uint32_t smem_u32(const void* p) {
    uint32_t a;
    asm("{ .reg .u64 t; cvta.to.shared.u64 t, %1; cvt.u32.u64 %0, t; }" : "=r"(a) : "l"(p));
    return a;
}
#define CP16(dst, src, nb) asm volatile("cp.async.cg.shared.global [%0], [%1], 16, %2;" :: "r"(dst), "l"(src), "r"(nb) : "memory")
#define CP_COMMIT() asm volatile("cp.async.commit_group;" ::: "memory")
#define CP_WAIT(n)  asm volatile("cp.async.wait_group %0;" :: "n"(n) : "memory")

#define LDSM4(r0, r1, r2, r3, addr) \
    asm volatile("ldmatrix.sync.aligned.m8n8.x4.shared.b16 {%0,%1,%2,%3}, [%4];" \
        : "=r"(r0), "=r"(r1), "=r"(r2), "=r"(r3) : "r"(addr))

#define MMA(d, a, b0_, b1_) \
    asm volatile("mma.sync.aligned.m16n8k16.row.col.f32.f16.f16.f32 " \
        "{%0,%1,%2,%3}, {%4,%5,%6,%7}, {%8,%9}, {%0,%1,%2,%3};" \
        : "+f"((d)[0]), "+f"((d)[1]), "+f"((d)[2]), "+f"((d)[3]) \
        : "r"((a)[0]), "r"((a)[1]), "r"((a)[2]), "r"((a)[3]), "r"(b0_), "r"(b1_))

// ---------------- LIF -> spikes NHWC fp16 (64ch/thread: 128B full-line stores) ----------------
__global__ void __launch_bounds__(256) lif_kernel(const float* __restrict__ x) {
    int px = blockIdx.x * 256 + threadIdx.x;
    int cc0 = blockIdx.y * 64, b = blockIdx.z;
    float v[64];
#pragma unroll
    for (int c = 0; c < 64; c++) v[c] = 0.0f;
#pragma unroll
    for (int t = 0; t < 4; t++) {
        const float* xp = x + ((size_t)(t * 8 + b) * 256 + cc0) * HW + px;
        uint4* dst = (uint4*)(g_spk + ((size_t)(t * 8 + b) * HW + px) * 256 + cc0);
#pragma unroll
        for (int q = 0; q < 8; q++) {
            unsigned pk[4];
#pragma unroll
            for (int cc = 0; cc < 8; cc++) {
                int c = q * 8 + cc;
                float xv = xp[(size_t)c * HW];
                float nv = v[c] + (xv - v[c]) * 0.5f;
                unsigned s = (nv >= 1.0f) ? 0x3C00u : 0u;
                v[c] = nv - ((nv >= 1.0f) ? 1.0f : 0.0f);
                if (cc & 1) pk[cc >> 1] |= (s << 16); else pk[cc >> 1] = s;
            }
            dst[q] = make_uint4(pk[0], pk[1], pk[2], pk[3]);
        }
    }
}

// ---------------- weight prep (pre-swizzled gmem tiles) ----------------
__global__ void prep1_kernel(const float* __restrict__ w1) {
    int i = blockIdx.x * 256 + threadIdx.x;           // 36*192*64
    if (i >= 36 * 192 * 64) return;
    int j = i & 63, row = (i >> 6) % 192, it = (i >> 6) / 192;
    int tap = it >> 2, c = (it & 3) * 64 + j;
    float w = w1[((size_t)row * 256 + c) * 9 + tap];
    g_wb1[(size_t)it * 12288 + row * 64 + (((j >> 3) ^ (row & 7)) * 8) + (j & 7)] = __float2half(w);
}
__global__ void prep2_kernel(const float* __restrict__ w2) {
    int i = blockIdx.x * 256 + threadIdx.x;           // 36*80*64
    if (i >= 36 * 80 * 64) return;
    int j = i & 63, row = (i >> 6) % 80, tg = (i >> 6) / 80;
    int g = tg & 3, tap = tg >> 2;
    unsigned short v = 0;
    if (j < 48) {
        float w = w2[(((size_t)(g * 80 + row)) * 48 + j) * 9 + tap];
        v = (w > 0.0f) ? 0x3C00u : ((w < 0.0f) ? 0xBC00u : 0u);
    }
    *(unsigned short*)&g_wb2[(size_t)tg * 5120 + row * 64 + (((j >> 3) ^ (row & 7)) * 8) + (j & 7)] = v;
}

// ================= conv1: 128px x 192oc per CTA, 384 threads (12 warps 2Mx6N) =================
// it = chunk*9 + tap; B tile index = tap*4 + chunk; warp tile = 64px x 32oc
// A: halo 264 rows x 128B = 33792B x2 buffers; B: 192x128B = 24576B x4 stages
// smem: A0 @0, A1 @33792, B @67584 + s*24576 ; total 165888
#define C1_SMEM 165888

__device__ __forceinline__ void c1_agran(uint32_t Ab, int n, int y0, int chunk, int g) {
    int idx = g >> 3, j = g & 7;
    int hy = idx / 66, hx = idx - hy * 66;
    int y = y0 - 1 + hy, x = hx - 1;
    bool ok = ((unsigned)y < 64u) & ((unsigned)x < 64u);
    const char* spk = (const char*)g_spk;
    size_t off = ((((size_t)n * HW) + (size_t)y * 64 + x) * 256 + chunk * 64 + j * 8) * 2;
    CP16(Ab + idx * 128 + (((unsigned)(j ^ (idx & 7))) << 4), ok ? (spk + off) : spk, ok ? 16 : 0);
}

__global__ void __launch_bounds__(384, 1) conv1_kernel() {
    extern __shared__ char sm[];
    uint32_t sb = smem_u32(sm);
    int tid = threadIdx.x, l = tid & 31, wid = tid >> 5;
    int wm = wid & 1, wn = wid >> 1;                 // 2 M-warps x 6 N-warps
    int n = blockIdx.x >> 5, y0 = (blockIdx.x & 31) * 2;

    int mat = l >> 3, mr = l & 7;
    int a_rl = (mat & 1) * 8 + mr, a_kh = mat >> 1;
    int b_nl = (mat >> 1) * 8 + mr, b_kh = mat & 1;

    float acc[4][4][4];                              // [mt][jn][q]
#pragma unroll
    for (int i = 0; i < 4; i++)
#pragma unroll
        for (int jn = 0; jn < 4; jn++)
#pragma unroll
            for (int q = 0; q < 4; q++) acc[i][jn][q] = 0.0f;

    // prologue: A(chunk0), B(it=0 -> tile 0), B(it=1 -> tile 4)
#pragma unroll
    for (int ii = 0; ii < 6; ii++) {
        int g = tid + ii * 384;
        if (g < 2112) c1_agran(sb, n, y0, 0, g);
    }
    CP_COMMIT();
#pragma unroll
    for (int s = 0; s < 2; s++) {
        const char* wb = (const char*)g_wb1 + (size_t)(s * 4) * 24576;
        uint32_t Bb = sb + 67584u + (uint32_t)s * 24576u;
#pragma unroll
        for (int ii = 0; ii < 4; ii++) {
            int lin = tid + ii * 384;
            CP16(Bb + lin * 16, wb + lin * 16, 16);
        }
        CP_COMMIT();
    }

    int tap = 0, c = 0;          // decomposition of it
    int tap2 = 2, c2 = 0;        // decomposition of it+2
    for (int it = 0; it < 36; it++) {
        if (it < 34) {
            const char* wb = (const char*)g_wb1 + (size_t)(tap2 * 4 + c2) * 24576;
            uint32_t Bb = sb + 67584u + (uint32_t)((it + 2) & 3) * 24576u;
#pragma unroll
            for (int ii = 0; ii < 4; ii++) {
                int lin = tid + ii * 384;
                CP16(Bb + lin * 16, wb + lin * 16, 16);
            }
        }
        if (tap >= 1 && tap <= 6 && c < 3 && tid < 352) {
            uint32_t Ab = sb + (uint32_t)((c + 1) & 1) * 33792u;
            c1_agran(Ab, n, y0, c + 1, (tap - 1) * 352 + tid);
        }
        CP_COMMIT();
        CP_WAIT(2);
        __syncthreads();

        uint32_t Ahb = sb + (uint32_t)(c & 1) * 33792u;
        uint32_t Bb = sb + 67584u + (uint32_t)(it & 3) * 24576u;
        int ky = tap / 3, kx = tap - ky * 3;
        int aib = (wm + ky) * 66 + kx + a_rl;
#pragma unroll
        for (int ks = 0; ks < 4; ks++) {
            uint32_t a[4][4];
#pragma unroll
            for (int mt = 0; mt < 4; mt++) {
                int idx = aib + mt * 16;
                uint32_t ad = Ahb + (uint32_t)(idx * 128 + ((((ks << 1) + a_kh) ^ (idx & 7)) << 4));
                LDSM4(a[mt][0], a[mt][1], a[mt][2], a[mt][3], ad);
            }
#pragma unroll
            for (int p = 0; p < 2; p++) {
                int row = wn * 32 + p * 16 + b_nl;
                uint32_t bd = Bb + (uint32_t)(row * 128 + ((((ks << 1) + b_kh) ^ (row & 7)) << 4));
                uint32_t b0, b1, b2, b3;
                LDSM4(b0, b1, b2, b3, bd);
#pragma unroll
                for (int mt = 0; mt < 4; mt++) {
                    MMA(acc[mt][p * 2],     a[mt], b0, b1);
                    MMA(acc[mt][p * 2 + 1], a[mt], b2, b3);
                }
            }
        }
        if (++tap == 9) { tap = 0; c++; }
        if (++tap2 == 9) { tap2 = 0; c2++; }
    }
    // epilogue: NHWC f32 stores + fused BN partials
    float lsum[8], lsq[8];
#pragma unroll
    for (int j = 0; j < 8; j++) { lsum[j] = 0.0f; lsq[j] = 0.0f; }

    size_t pixbase = (size_t)n * HW + (size_t)y0 * 64;
    int c0 = wn * 32 + (l & 3) * 2;
#pragma unroll
    for (int mt = 0; mt < 4; mt++) {
        size_t row = pixbase + wm * 64 + mt * 16 + (l >> 2);
#pragma unroll
        for (int jn = 0; jn < 4; jn++) {
            float* d = acc[mt][jn];
            lsum[jn * 2]     += d[0] + d[2];
            lsum[jn * 2 + 1] += d[1] + d[3];
            lsq[jn * 2]      += d[0] * d[0] + d[2] * d[2];
            lsq[jn * 2 + 1]  += d[1] * d[1] + d[3] * d[3];
            int col = c0 + jn * 8;
            *(float2*)&g_y[row * 192 + col]       = make_float2(d[0], d[1]);
            *(float2*)&g_y[(row + 8) * 192 + col] = make_float2(d[2], d[3]);
        }
    }
    // deterministic cross-thread reduction of BN partials (oc-major)
    __syncthreads();
    float* ssum = (float*)sm;                 // 384*8 floats
    float* ssq  = (float*)(sm + 16384);
#pragma unroll
    for (int j = 0; j < 8; j++) { ssum[tid * 8 + j] = lsum[j]; ssq[tid * 8 + j] = lsq[j]; }
    __syncthreads();
    if (tid < 192) {
        int wn_ = tid >> 5, r = tid & 31;
        int jn = r >> 3, rem = r & 7, l3 = rem >> 1, cp = rem & 1;
        int j = jn * 2 + cp;
        float s = 0.0f, q = 0.0f;
#pragma unroll
        for (int wm_ = 0; wm_ < 2; wm_++)
#pragma unroll
            for (int lr = 0; lr < 8; lr++) {
                int ct = ((wn_ * 2 + wm_) * 32 + lr * 4 + l3) * 8 + j;
                s += ssum[ct]; q += ssq[ct];
            }
        g_p1[blockIdx.x * 192 + tid] = s;
        g_p2[blockIdx.x * 192 + tid] = q;
    }
}

// ---------------- BN finalize (reads 1024 per-CTA partials, fixed order) ----------------
__global__ void bn_final_kernel(const float* __restrict__ gamma, const float* __restrict__ beta) {
    int c = blockIdx.x, t = threadIdx.x;
    float s = 0, q = 0;
    for (int i = t; i < 1024; i += 64) { s += g_p1[i * 192 + c]; q += g_p2[i * 192 + c]; }
    __shared__ float ss[64], sq[64];
    ss[t] = s; sq[t] = q; __syncthreads();
    for (int o = 32; o > 0; o >>= 1) {
        if (t < o) { ss[t] += ss[t + o]; sq[t] += sq[t + o]; }
        __syncthreads();
    }
    if (t == 0) {
        float m = ss[0] / 131072.0f;
        float var = sq[0] / 131072.0f - m * m;
        float sc = rsqrtf(var + 1e-5f) * gamma[c];
        g_scale[c] = sc; g_shift[c] = beta[c] - m * sc;
    }
}

// ---------------- BN apply: x1 (NCHW out) + g_ybh (padded NHWC fp16) ----------------
__global__ void __launch_bounds__(256) bn_apply_kernel(float* __restrict__ out) {
    __shared__ float smt[192 * 33];
    int n = blockIdx.y, px0 = blockIdx.x * 32;
    for (int i = threadIdx.x; i < 32 * 256; i += 256) {
        int pl = i >> 8, cp = i & 255;
        int g = cp >> 6, sft = cp & 63;
        size_t pix = (size_t)n * HW + px0 + pl;
        float r = 0.0f;
        if (sft < 48) {
            int c = g * 48 + sft;
            float v = g_y[pix * 192 + c];
            r = v * g_scale[c] + g_shift[c];
            smt[c * 33 + pl] = r;
        }
        g_ybh[pix * 256 + cp] = __float2half(r);
    }
    __syncthreads();
    for (int j = threadIdx.x; j < 192 * 32; j += 256) {
        int c = j >> 5, pl = j & 31;
        out[((size_t)n * 512 + c) * HW + px0 + pl] = smt[c * 33 + pl];
    }
}

// ================= conv2: 128px x 80oc per CTA (one group) =================
// A: halo tile 264 x 128B = 33792B (single buffer, 9 taps share it)
// B: 80 x 128B = 10240B, 4 stages
// smem: A @0, B @33792 + s*10240; total 74752
#define C2_SMEM 74752

__device__ __forceinline__ void c2_agran(uint32_t Ab, int n, int y0, int grp, int g) {
    int idx = g >> 3, j = g & 7;
    int hy = idx / 66, hx = idx - hy * 66;
    int y = y0 - 1 + hy, x = hx - 1;
    bool ok = ((unsigned)y < 64u) & ((unsigned)x < 64u);
    const char* src = (const char*)g_ybh;
    size_t off = ((((size_t)n * HW) + (size_t)y * 64 + x) * 256 + grp * 64 + j * 8) * 2;
    CP16(Ab + idx * 128 + (((unsigned)(j ^ (idx & 7))) << 4), ok ? (src + off) : src, ok ? 16 : 0);
}

__global__ void __launch_bounds__(128, 3) conv2_kernel(float* __restrict__ out) {
    extern __shared__ char sm[];
    uint32_t sb = smem_u32(sm);
    int tid = threadIdx.x, l = tid & 31, wm = tid >> 5;   // 4 M-warps
    int g = blockIdx.x & 3, y0 = ((blockIdx.x >> 2) & 31) * 2, n = blockIdx.x >> 7;

    int mat = l >> 3, mr = l & 7;
    int a_rl = (mat & 1) * 8 + mr, a_kh = mat >> 1;
    int b_nl = (mat >> 1) * 8 + mr, b_kh = mat & 1;

    float acc[2][10][4];
#pragma unroll
    for (int i = 0; i < 2; i++)
#pragma unroll
        for (int jn = 0; jn < 10; jn++)
#pragma unroll
            for (int q = 0; q < 4; q++) acc[i][jn][q] = 0.0f;

    // prologue: A halo, B(0), B(1)
#pragma unroll
    for (int ii = 0; ii < 17; ii++) {
        int gg = tid + ii * 128;
        if (gg < 2112) c2_agran(sb, n, y0, g, gg);
    }
    CP_COMMIT();
#pragma unroll
    for (int s = 0; s < 2; s++) {
        const char* wb = (const char*)g_wb2 + (size_t)(s * 4 + g) * 10240;
        uint32_t Bb = sb + 33792u + (uint32_t)s * 10240u;
#pragma unroll
        for (int ii = 0; ii < 5; ii++) {
            int lin = tid + ii * 128;
            CP16(Bb + lin * 16, wb + lin * 16, 16);
        }
        CP_COMMIT();
    }

    int ry = wm >> 1, rx = (wm & 1) * 32;
    for (int it = 0; it < 9; it++) {
        if (it < 7) {
            const char* wb = (const char*)g_wb2 + (size_t)((it + 2) * 4 + g) * 10240;
            uint32_t Bb = sb + 33792u + (uint32_t)((it + 2) & 3) * 10240u;
#pragma unroll
            for (int ii = 0; ii < 5; ii++) {
                int lin = tid + ii * 128;
                CP16(Bb + lin * 16, wb + lin * 16, 16);
            }
        }
        CP_COMMIT();
        CP_WAIT(2);
        __syncthreads();

        uint32_t Bb = sb + 33792u + (uint32_t)(it & 3) * 10240u;
        int ky = it / 3, kx = it - ky * 3;
        int aib = (ry + ky) * 66 + kx + rx + a_rl;
#pragma unroll
        for (int ks = 0; ks < 4; ks++) {
            uint32_t a[2][4];
#pragma unroll
            for (int mt = 0; mt < 2; mt++) {
                int idx = aib + mt * 16;
                uint32_t ad = sb + (uint32_t)(idx * 128 + ((((ks << 1) + a_kh) ^ (idx & 7)) << 4));
                LDSM4(a[mt][0], a[mt][1], a[mt][2], a[mt][3], ad);
            }
#pragma unroll
            for (int p = 0; p < 5; p++) {
                int row = p * 16 + b_nl;
                uint32_t bd = Bb + (uint32_t)(row * 128 + ((((ks << 1) + b_kh) ^ (row & 7)) << 4));
                uint32_t b0, b1, b2, b3;
                LDSM4(b0, b1, b2, b3, bd);
#pragma unroll
                for (int mt = 0; mt < 2; mt++) {
                    MMA(acc[mt][p * 2],     a[mt], b0, b1);
                    MMA(acc[mt][p * 2 + 1], a[mt], b2, b3);
                }
            }
        }
    }
    // epilogue: NCHW stores into x2 slice (8-consecutive-row fragments = full sectors)
    float* ob = out + ((size_t)n * 512 + 192 + (size_t)g * 80) * HW + (size_t)y0 * 64;
    int r0 = wm * 32 + (l >> 2), c0 = (l & 3) * 2;
#pragma unroll
    for (int mt = 0; mt < 2; mt++)
#pragma unroll
        for (int nt = 0; nt < 10; nt++) {
            float* d = acc[mt][nt];
            int row = r0 + mt * 16, col = c0 + nt * 8;
            ob[(size_t)col * HW + row]           = d[0];
            ob[(size_t)(col + 1) * HW + row]     = d[1];
            ob[(size_t)col * HW + row + 8]       = d[2];
            ob[(size_t)(col + 1) * HW + row + 8] = d[3];
        }
}

// ---------------- launch ----------------
extern "C" void kernel_launch(void* const* d_in, const int* in_sizes, int n_in,
                              void* d_out, int out_size) {
    const float* x     = (const float*)d_in[0];
    const float* w1    = (const float*)d_in[1];
    const float* gamma = (const float*)d_in[2];
    const float* beta  = (const float*)d_in[3];
    const float* w2    = (const float*)d_in[4];
    float* out = (float*)d_out;

    cudaFuncSetAttribute(conv1_kernel, cudaFuncAttributeMaxDynamicSharedMemorySize, C1_SMEM);
    cudaFuncSetAttribute(conv2_kernel, cudaFuncAttributeMaxDynamicSharedMemorySize, C2_SMEM);

    lif_kernel  <<<dim3(16, 4, 8), 256>>>(x);
    prep1_kernel<<<1728, 256>>>(w1);
    prep2_kernel<<<720, 256>>>(w2);

    conv1_kernel<<<1024, 384, C1_SMEM>>>();   // writes g_y + BN partials

    bn_final_kernel<<<192, 64>>>(gamma, beta);
    bn_apply_kernel<<<dim3(128, 32), 256>>>(out);

    conv2_kernel<<<4096, 128, C2_SMEM>>>(out);
}

// round 12
// speedup vs baseline: 1.0358x; 1.0358x over previous
#include <cuda_runtime.h>
#include <cuda_fp16.h>
#include <cstdint>

#define NNI 32
#define HW  4096

// ---------------- scratch ----------------
__device__ __align__(128) __half g_spk[(size_t)NNI * HW * 256];   // spikes NHWC fp16
__device__ __align__(128) float  g_y  [(size_t)NNI * HW * 192];   // conv1 out NHWC f32
__device__ __align__(128) __half g_ybh[(size_t)NNI * HW * 256];   // BN out fp16 (4x64 padded)
__device__ __align__(128) __half g_wb1[36 * 192 * 64];            // [tap*4+chunk][192][64] swizzled
__device__ __align__(128) __half g_wb2[36 * 80 * 64];             // [tap*4+g][80][64] sign, swizzled
__device__ float g_p1[1024 * 192], g_p2[1024 * 192];              // per-conv1-CTA BN partials
__device__ float g_scale[192], g_shift[192];

// ---------------- PTX helpers (sm_80-compatible only) ----------------
__device__ __forceinline__ uint32_t smem_u32(const void* p) {
    uint32_t a;
    asm("{ .reg .u64 t; cvta.to.shared.u64 t, %1; cvt.u32.u64 %0, t; }" : "=r"(a) : "l"(p));
    return a;
}
#define CP16(dst, src, nb) asm volatile("cp.async.cg.shared.global [%0], [%1], 16, %2;" :: "r"(dst), "l"(src), "r"(nb) : "memory")
#define CP_COMMIT() asm volatile("cp.async.commit_group;" ::: "memory")
#define CP_WAIT(n)  asm volatile("cp.async.wait_group %0;" :: "n"(n) : "memory")

#define LDSM4(r0, r1, r2, r3, addr) \
    asm volatile("ldmatrix.sync.aligned.m8n8.x4.shared.b16 {%0,%1,%2,%3}, [%4];" \
        : "=r"(r0), "=r"(r1), "=r"(r2), "=r"(r3) : "r"(addr))

#define MMA(d, a, b0_, b1_) \
    asm volatile("mma.sync.aligned.m16n8k16.row.col.f32.f16.f16.f32 " \
        "{%0,%1,%2,%3}, {%4,%5,%6,%7}, {%8,%9}, {%0,%1,%2,%3};" \
        : "+f"((d)[0]), "+f"((d)[1]), "+f"((d)[2]), "+f"((d)[3]) \
        : "r"((a)[0]), "r"((a)[1]), "r"((a)[2]), "r"((a)[3]), "r"(b0_), "r"(b1_))

// ---------------- LIF -> spikes NHWC fp16 (64ch/thread: 128B full-line stores) ----------------
__global__ void __launch_bounds__(256) lif_kernel(const float* __restrict__ x) {
    int px = blockIdx.x * 256 + threadIdx.x;
    int cc0 = blockIdx.y * 64, b = blockIdx.z;
    float v[64];
#pragma unroll
    for (int c = 0; c < 64; c++) v[c] = 0.0f;
#pragma unroll
    for (int t = 0; t < 4; t++) {
        const float* xp = x + ((size_t)(t * 8 + b) * 256 + cc0) * HW + px;
        uint4* dst = (uint4*)(g_spk + ((size_t)(t * 8 + b) * HW + px) * 256 + cc0);
#pragma unroll
        for (int q = 0; q < 8; q++) {
            unsigned pk[4];
#pragma unroll
            for (int cc = 0; cc < 8; cc++) {
                int c = q * 8 + cc;
                float xv = xp[(size_t)c * HW];
                float nv = v[c] + (xv - v[c]) * 0.5f;
                unsigned s = (nv >= 1.0f) ? 0x3C00u : 0u;
                v[c] = nv - ((nv >= 1.0f) ? 1.0f : 0.0f);
                if (cc & 1) pk[cc >> 1] |= (s << 16); else pk[cc >> 1] = s;
            }
            dst[q] = make_uint4(pk[0], pk[1], pk[2], pk[3]);
        }
    }
}

// ---------------- weight prep (pre-swizzled gmem tiles) ----------------
__global__ void prep1_kernel(const float* __restrict__ w1) {
    int i = blockIdx.x * 256 + threadIdx.x;           // 36*192*64
    if (i >= 36 * 192 * 64) return;
    int j = i & 63, row = (i >> 6) % 192, it = (i >> 6) / 192;
    int tap = it >> 2, c = (it & 3) * 64 + j;
    float w = w1[((size_t)row * 256 + c) * 9 + tap];
    g_wb1[(size_t)it * 12288 + row * 64 + (((j >> 3) ^ (row & 7)) * 8) + (j & 7)] = __float2half(w);
}
__global__ void prep2_kernel(const float* __restrict__ w2) {
    int i = blockIdx.x * 256 + threadIdx.x;           // 36*80*64
    if (i >= 36 * 80 * 64) return;
    int j = i & 63, row = (i >> 6) % 80, tg = (i >> 6) / 80;
    int g = tg & 3, tap = tg >> 2;
    unsigned short v = 0;
    if (j < 48) {
        float w = w2[(((size_t)(g * 80 + row)) * 48 + j) * 9 + tap];
        v = (w > 0.0f) ? 0x3C00u : ((w < 0.0f) ? 0xBC00u : 0u);
    }
    *(unsigned short*)&g_wb2[(size_t)tg * 5120 + row * 64 + (((j >> 3) ^ (row & 7)) * 8) + (j & 7)] = v;
}

// ================= conv1: 128px x 192oc per CTA, 256 threads (8 warps 2Mx4N) =================
// it = chunk*9 + tap; B tile index = tap*4 + chunk
// A: halo 264 rows x 128B = 33792B x2 buffers; B: 192x128B = 24576B x4 stages
// smem: A0 @0, A1 @33792, B @67584 + s*24576 ; total 165888
// Sync cadence: CP_WAIT(0)+__syncthreads only on EVEN iterations; prefetch issue AFTER barrier.
#define C1_SMEM 165888

__device__ __forceinline__ void c1_agran(uint32_t Ab, int n, int y0, int chunk, int g) {
    int idx = g >> 3, j = g & 7;
    int hy = idx / 66, hx = idx - hy * 66;
    int y = y0 - 1 + hy, x = hx - 1;
    bool ok = ((unsigned)y < 64u) & ((unsigned)x < 64u);
    const char* spk = (const char*)g_spk;
    size_t off = ((((size_t)n * HW) + (size_t)y * 64 + x) * 256 + chunk * 64 + j * 8) * 2;
    CP16(Ab + idx * 128 + (((unsigned)(j ^ (idx & 7))) << 4), ok ? (spk + off) : spk, ok ? 16 : 0);
}

__global__ void __launch_bounds__(256, 1) conv1_kernel() {
    extern __shared__ char sm[];
    uint32_t sb = smem_u32(sm);
    int tid = threadIdx.x, l = tid & 31, wid = tid >> 5;
    int wm = wid & 1, wn = wid >> 1;                 // 2 M-warps x 4 N-warps
    int n = blockIdx.x >> 5, y0 = (blockIdx.x & 31) * 2;

    int mat = l >> 3, mr = l & 7;
    int a_rl = (mat & 1) * 8 + mr, a_kh = mat >> 1;
    int b_nl = (mat >> 1) * 8 + mr, b_kh = mat & 1;

    float acc[4][6][4];
#pragma unroll
    for (int i = 0; i < 4; i++)
#pragma unroll
        for (int jn = 0; jn < 6; jn++)
#pragma unroll
            for (int q = 0; q < 4; q++) acc[i][jn][q] = 0.0f;

    // prologue: A(chunk0), B(it=0 -> tile 0), B(it=1 -> tile 4)
#pragma unroll
    for (int ii = 0; ii < 9; ii++) {
        int g = tid + ii * 256;
        if (g < 2112) c1_agran(sb, n, y0, 0, g);
    }
#pragma unroll
    for (int s = 0; s < 2; s++) {
        const char* wb = (const char*)g_wb1 + (size_t)(s * 4) * 24576;
        uint32_t Bb = sb + 67584u + (uint32_t)s * 24576u;
#pragma unroll
        for (int ii = 0; ii < 6; ii++) {
            int lin = tid + ii * 256;
            CP16(Bb + lin * 16, wb + lin * 16, 16);
        }
    }
    CP_COMMIT();

    int tap = 0, c = 0;          // decomposition of it
    int tap2 = 2, c2 = 0;        // decomposition of it+2
    for (int it = 0; it < 36; it++) {
        if ((it & 1) == 0) {     // sync point every 2 iterations
            CP_WAIT(0);
            __syncthreads();
        }
        // prefetch B(it+2) (after barrier: safe stage reuse)
        if (it < 34) {
            const char* wb = (const char*)g_wb1 + (size_t)(tap2 * 4 + c2) * 24576;
            uint32_t Bb = sb + 67584u + (uint32_t)((it + 2) & 3) * 24576u;
#pragma unroll
            for (int ii = 0; ii < 6; ii++) {
                int lin = tid + ii * 256;
                CP16(Bb + lin * 16, wb + lin * 16, 16);
            }
        }
        // prefetch A(c+1) spread over taps 1..6
        if (tap >= 1 && tap <= 6 && c < 3) {
            uint32_t Ab = sb + (uint32_t)((c + 1) & 1) * 33792u;
            int g0 = (tap - 1) * 352 + tid;
            c1_agran(Ab, n, y0, c + 1, g0);
            if (tid < 96) c1_agran(Ab, n, y0, c + 1, g0 + 256);
        }
        CP_COMMIT();

        uint32_t Ahb = sb + (uint32_t)(c & 1) * 33792u;
        uint32_t Bb = sb + 67584u + (uint32_t)(it & 3) * 24576u;
        int ky = tap / 3, kx = tap - ky * 3;
        int aib = (wm + ky) * 66 + kx + a_rl;
#pragma unroll
        for (int ks = 0; ks < 4; ks++) {
            uint32_t a[4][4];
#pragma unroll
            for (int mt = 0; mt < 4; mt++) {
                int idx = aib + mt * 16;
                uint32_t ad = Ahb + (uint32_t)(idx * 128 + ((((ks << 1) + a_kh) ^ (idx & 7)) << 4));
                LDSM4(a[mt][0], a[mt][1], a[mt][2], a[mt][3], ad);
            }
#pragma unroll
            for (int p = 0; p < 3; p++) {
                int row = wn * 48 + p * 16 + b_nl;
                uint32_t bd = Bb + (uint32_t)(row * 128 + ((((ks << 1) + b_kh) ^ (row & 7)) << 4));
                uint32_t b0, b1, b2, b3;
                LDSM4(b0, b1, b2, b3, bd);
#pragma unroll
                for (int mt = 0; mt < 4; mt++) {
                    MMA(acc[mt][p * 2],     a[mt], b0, b1);
                    MMA(acc[mt][p * 2 + 1], a[mt], b2, b3);
                }
            }
        }
        if (++tap == 9) { tap = 0; c++; }
        if (++tap2 == 9) { tap2 = 0; c2++; }
    }
    // epilogue: NHWC f32 stores + fused BN partials
    float lsum[12], lsq[12];
#pragma unroll
    for (int j = 0; j < 12; j++) { lsum[j] = 0.0f; lsq[j] = 0.0f; }

    size_t pixbase = (size_t)n * HW + (size_t)y0 * 64;
    int c0 = wn * 48 + (l & 3) * 2;
#pragma unroll
    for (int mt = 0; mt < 4; mt++) {
        size_t row = pixbase + wm * 64 + mt * 16 + (l >> 2);
#pragma unroll
        for (int p = 0; p < 6; p++) {
            float* d = acc[mt][p];
#pragma unroll
            for (int q = 0; q < 4; q++) {
                float v = d[q];
                int j = p * 2 + (q & 1);
                lsum[j] += v; lsq[j] += v * v;
            }
            int col = c0 + p * 8;
            *(float2*)&g_y[row * 192 + col]       = make_float2(d[0], d[1]);
            *(float2*)&g_y[(row + 8) * 192 + col] = make_float2(d[2], d[3]);
        }
    }
    // deterministic cross-thread reduction of BN partials (oc-major)
    __syncthreads();
    float* ssum = (float*)sm;                 // 256*12 floats
    float* ssq  = (float*)(sm + 16384);
#pragma unroll
    for (int j = 0; j < 12; j++) { ssum[tid * 12 + j] = lsum[j]; ssq[tid * 12 + j] = lsq[j]; }
    __syncthreads();
    if (tid < 192) {
        int wn_ = tid / 48, r = tid % 48;
        int p = r >> 3, l2 = (r & 7) >> 1, cp = r & 1;
        int j = p * 2 + cp;
        float s = 0.0f, q = 0.0f;
#pragma unroll
        for (int wm_ = 0; wm_ < 2; wm_++)
#pragma unroll
            for (int lr = 0; lr < 8; lr++) {
                int ct = ((wn_ * 2 + wm_) * 32 + lr * 4 + l2) * 12 + j;
                s += ssum[ct]; q += ssq[ct];
            }
        g_p1[blockIdx.x * 192 + tid] = s;
        g_p2[blockIdx.x * 192 + tid] = q;
    }
}

// ---------------- BN finalize (reads 1024 per-CTA partials, fixed order) ----------------
__global__ void bn_final_kernel(const float* __restrict__ gamma, const float* __restrict__ beta) {
    int c = blockIdx.x, t = threadIdx.x;
    float s = 0, q = 0;
    for (int i = t; i < 1024; i += 64) { s += g_p1[i * 192 + c]; q += g_p2[i * 192 + c]; }
    __shared__ float ss[64], sq[64];
    ss[t] = s; sq[t] = q; __syncthreads();
    for (int o = 32; o > 0; o >>= 1) {
        if (t < o) { ss[t] += ss[t + o]; sq[t] += sq[t + o]; }
        __syncthreads();
    }
    if (t == 0) {
        float m = ss[0] / 131072.0f;
        float var = sq[0] / 131072.0f - m * m;
        float sc = rsqrtf(var + 1e-5f) * gamma[c];
        g_scale[c] = sc; g_shift[c] = beta[c] - m * sc;
    }
}

// ---------------- BN apply: x1 (NCHW out) + g_ybh (padded NHWC fp16) ----------------
__global__ void __launch_bounds__(256) bn_apply_kernel(float* __restrict__ out) {
    __shared__ float smt[192 * 33];
    int n = blockIdx.y, px0 = blockIdx.x * 32;
    for (int i = threadIdx.x; i < 32 * 256; i += 256) {
        int pl = i >> 8, cp = i & 255;
        int g = cp >> 6, sft = cp & 63;
        size_t pix = (size_t)n * HW + px0 + pl;
        float r = 0.0f;
        if (sft < 48) {
            int c = g * 48 + sft;
            float v = g_y[pix * 192 + c];
            r = v * g_scale[c] + g_shift[c];
            smt[c * 33 + pl] = r;
        }
        g_ybh[pix * 256 + cp] = __float2half(r);
    }
    __syncthreads();
    for (int j = threadIdx.x; j < 192 * 32; j += 256) {
        int c = j >> 5, pl = j & 31;
        out[((size_t)n * 512 + c) * HW + px0 + pl] = smt[c * 33 + pl];
    }
}

// ================= conv2: 128px x 80oc per CTA (one group) =================
// A: halo tile 264 x 128B = 33792B (single buffer, 9 taps share it)
// B: 80 x 128B = 10240B, 4 stages
// smem: A @0, B @33792 + s*10240; total 74752
#define C2_SMEM 74752

__device__ __forceinline__ void c2_agran(uint32_t Ab, int n, int y0, int grp, int g) {
    int idx = g >> 3, j = g & 7;
    int hy = idx / 66, hx = idx - hy * 66;
    int y = y0 - 1 + hy, x = hx - 1;
    bool ok = ((unsigned)y < 64u) & ((unsigned)x < 64u);
    const char* src = (const char*)g_ybh;
    size_t off = ((((size_t)n * HW) + (size_t)y * 64 + x) * 256 + grp * 64 + j * 8) * 2;
    CP16(Ab + idx * 128 + (((unsigned)(j ^ (idx & 7))) << 4), ok ? (src + off) : src, ok ? 16 : 0);
}

__global__ void __launch_bounds__(128, 3) conv2_kernel(float* __restrict__ out) {
    extern __shared__ char sm[];
    uint32_t sb = smem_u32(sm);
    int tid = threadIdx.x, l = tid & 31, wm = tid >> 5;   // 4 M-warps
    int g = blockIdx.x & 3, y0 = ((blockIdx.x >> 2) & 31) * 2, n = blockIdx.x >> 7;

    int mat = l >> 3, mr = l & 7;
    int a_rl = (mat & 1) * 8 + mr, a_kh = mat >> 1;
    int b_nl = (mat >> 1) * 8 + mr, b_kh = mat & 1;

    float acc[2][10][4];
#pragma unroll
    for (int i = 0; i < 2; i++)
#pragma unroll
        for (int jn = 0; jn < 10; jn++)
#pragma unroll
            for (int q = 0; q < 4; q++) acc[i][jn][q] = 0.0f;

    // prologue: A halo, B(0), B(1)
#pragma unroll
    for (int ii = 0; ii < 17; ii++) {
        int gg = tid + ii * 128;
        if (gg < 2112) c2_agran(sb, n, y0, g, gg);
    }
    CP_COMMIT();
#pragma unroll
    for (int s = 0; s < 2; s++) {
        const char* wb = (const char*)g_wb2 + (size_t)(s * 4 + g) * 10240;
        uint32_t Bb = sb + 33792u + (uint32_t)s * 10240u;
#pragma unroll
        for (int ii = 0; ii < 5; ii++) {
            int lin = tid + ii * 128;
            CP16(Bb + lin * 16, wb + lin * 16, 16);
        }
        CP_COMMIT();
    }

    int ry = wm >> 1, rx = (wm & 1) * 32;
    for (int it = 0; it < 9; it++) {
        if (it < 7) {
            const char* wb = (const char*)g_wb2 + (size_t)((it + 2) * 4 + g) * 10240;
            uint32_t Bb = sb + 33792u + (uint32_t)((it + 2) & 3) * 10240u;
#pragma unroll
            for (int ii = 0; ii < 5; ii++) {
                int lin = tid + ii * 128;
                CP16(Bb + lin * 16, wb + lin * 16, 16);
            }
        }
        CP_COMMIT();
        CP_WAIT(2);
        __syncthreads();

        uint32_t Bb = sb + 33792u + (uint32_t)(it & 3) * 10240u;
        int ky = it / 3, kx = it - ky * 3;
        int aib = (ry + ky) * 66 + kx + rx + a_rl;
#pragma unroll
        for (int ks = 0; ks < 4; ks++) {
            uint32_t a[2][4];
#pragma unroll
            for (int mt = 0; mt < 2; mt++) {
                int idx = aib + mt * 16;
                uint32_t ad = sb + (uint32_t)(idx * 128 + ((((ks << 1) + a_kh) ^ (idx & 7)) << 4));
                LDSM4(a[mt][0], a[mt][1], a[mt][2], a[mt][3], ad);
            }
#pragma unroll
            for (int p = 0; p < 5; p++) {
                int row = p * 16 + b_nl;
                uint32_t bd = Bb + (uint32_t)(row * 128 + ((((ks << 1) + b_kh) ^ (row & 7)) << 4));
                uint32_t b0, b1, b2, b3;
                LDSM4(b0, b1, b2, b3, bd);
#pragma unroll
                for (int mt = 0; mt < 2; mt++) {
                    MMA(acc[mt][p * 2],     a[mt], b0, b1);
                    MMA(acc[mt][p * 2 + 1], a[mt], b2, b3);
                }
            }
        }
    }
    // epilogue: NCHW stores into x2 slice (8-consecutive-row fragments = full sectors)
    float* ob = out + ((size_t)n * 512 + 192 + (size_t)g * 80) * HW + (size_t)y0 * 64;
    int r0 = wm * 32 + (l >> 2), c0 = (l & 3) * 2;
#pragma unroll
    for (int mt = 0; mt < 2; mt++)
#pragma unroll
        for (int nt = 0; nt < 10; nt++) {
            float* d = acc[mt][nt];
            int row = r0 + mt * 16, col = c0 + nt * 8;
            ob[(size_t)col * HW + row]           = d[0];
            ob[(size_t)(col + 1) * HW + row]     = d[1];
            ob[(size_t)col * HW + row + 8]       = d[2];
            ob[(size_t)(col + 1) * HW + row + 8] = d[3];
        }
}

// ---------------- launch ----------------
extern "C" void kernel_launch(void* const* d_in, const int* in_sizes, int n_in,
                              void* d_out, int out_size) {
    const float* x     = (const float*)d_in[0];
    const float* w1    = (const float*)d_in[1];
    const float* gamma = (const float*)d_in[2];
    const float* beta  = (const float*)d_in[3];
    const float* w2    = (const float*)d_in[4];
    float* out = (float*)d_out;

    cudaFuncSetAttribute(conv1_kernel, cudaFuncAttributeMaxDynamicSharedMemorySize, C1_SMEM);
    cudaFuncSetAttribute(conv2_kernel, cudaFuncAttributeMaxDynamicSharedMemorySize, C2_SMEM);

    lif_kernel  <<<dim3(16, 4, 8), 256>>>(x);
    prep1_kernel<<<1728, 256>>>(w1);
    prep2_kernel<<<720, 256>>>(w2);

    conv1_kernel<<<1024, 256, C1_SMEM>>>();   // writes g_y + BN partials

    bn_final_kernel<<<192, 64>>>(gamma, beta);
    bn_apply_kernel<<<dim3(128, 32), 256>>>(out);

    conv2_kernel<<<4096, 128, C2_SMEM>>>(out);
}

// round 13
// speedup vs baseline: 1.0737x; 1.0367x over previous
#include <cuda_runtime.h>
#include <cuda_fp16.h>
#include <cstdint>

#define NNI 32
#define HW  4096

// ---------------- scratch ----------------
__device__ __align__(128) __half g_spk[(size_t)NNI * HW * 256];   // spikes NHWC fp16
__device__ __align__(128) float  g_y  [(size_t)NNI * HW * 192];   // conv1 out NHWC f32
__device__ __align__(128) __half g_ybh[(size_t)NNI * HW * 256];   // BN out fp16 (4x64 padded, ch48-63=0)
__device__ __align__(128) __half g_wb1[36 * 192 * 64];            // [tap*4+chunk][192][64] swizzled
__device__ __align__(128) __half g_wb2[36 * 80 * 64];             // [tap*4+g][80][64] sign, swizzled
__device__ float g_p1[1024 * 192], g_p2[1024 * 192];              // per-conv1-CTA BN partials
__device__ float g_scale[192], g_shift[192];

// ---------------- PTX helpers (sm_80-compatible only) ----------------
__device__ __forceinline__ uint32_t smem_u32(const void* p) {
    uint32_t a;
    asm("{ .reg .u64 t; cvta.to.shared.u64 t, %1; cvt.u32.u64 %0, t; }" : "=r"(a) : "l"(p));
    return a;
}
#define CP16(dst, src, nb) asm volatile("cp.async.cg.shared.global [%0], [%1], 16, %2;" :: "r"(dst), "l"(src), "r"(nb) : "memory")
#define CP_COMMIT() asm volatile("cp.async.commit_group;" ::: "memory")
#define CP_WAIT(n)  asm volatile("cp.async.wait_group %0;" :: "n"(n) : "memory")

#define LDSM4(r0, r1, r2, r3, addr) \
    asm volatile("ldmatrix.sync.aligned.m8n8.x4.shared.b16 {%0,%1,%2,%3}, [%4];" \
        : "=r"(r0), "=r"(r1), "=r"(r2), "=r"(r3) : "r"(addr))

#define MMA(d, a, b0_, b1_) \
    asm volatile("mma.sync.aligned.m16n8k16.row.col.f32.f16.f16.f32 " \
        "{%0,%1,%2,%3}, {%4,%5,%6,%7}, {%8,%9}, {%0,%1,%2,%3};" \
        : "+f"((d)[0]), "+f"((d)[1]), "+f"((d)[2]), "+f"((d)[3]) \
        : "r"((a)[0]), "r"((a)[1]), "r"((a)[2]), "r"((a)[3]), "r"(b0_), "r"(b1_))

// ---------------- LIF -> spikes NHWC fp16 (64ch/thread: 128B full-line stores) ----------------
__global__ void __launch_bounds__(256) lif_kernel(const float* __restrict__ x) {
    int px = blockIdx.x * 256 + threadIdx.x;
    int cc0 = blockIdx.y * 64, b = blockIdx.z;
    float v[64];
#pragma unroll
    for (int c = 0; c < 64; c++) v[c] = 0.0f;
#pragma unroll
    for (int t = 0; t < 4; t++) {
        const float* xp = x + ((size_t)(t * 8 + b) * 256 + cc0) * HW + px;
        uint4* dst = (uint4*)(g_spk + ((size_t)(t * 8 + b) * HW + px) * 256 + cc0);
#pragma unroll
        for (int q = 0; q < 8; q++) {
            unsigned pk[4];
#pragma unroll
            for (int cc = 0; cc < 8; cc++) {
                int c = q * 8 + cc;
                float xv = xp[(size_t)c * HW];
                float nv = v[c] + (xv - v[c]) * 0.5f;
                unsigned s = (nv >= 1.0f) ? 0x3C00u : 0u;
                v[c] = nv - ((nv >= 1.0f) ? 1.0f : 0.0f);
                if (cc & 1) pk[cc >> 1] |= (s << 16); else pk[cc >> 1] = s;
            }
            dst[q] = make_uint4(pk[0], pk[1], pk[2], pk[3]);
        }
    }
}

// ---------------- weight prep (pre-swizzled gmem tiles) ----------------
__global__ void prep1_kernel(const float* __restrict__ w1) {
    int i = blockIdx.x * 256 + threadIdx.x;           // 36*192*64
    if (i >= 36 * 192 * 64) return;
    int j = i & 63, row = (i >> 6) % 192, it = (i >> 6) / 192;
    int tap = it >> 2, c = (it & 3) * 64 + j;
    float w = w1[((size_t)row * 256 + c) * 9 + tap];
    g_wb1[(size_t)it * 12288 + row * 64 + (((j >> 3) ^ (row & 7)) * 8) + (j & 7)] = __float2half(w);
}
__global__ void prep2_kernel(const float* __restrict__ w2) {
    int i = blockIdx.x * 256 + threadIdx.x;           // 36*80*64
    if (i >= 36 * 80 * 64) return;
    int j = i & 63, row = (i >> 6) % 80, tg = (i >> 6) / 80;
    int g = tg & 3, tap = tg >> 2;
    unsigned short v = 0;
    if (j < 48) {
        float w = w2[(((size_t)(g * 80 + row)) * 48 + j) * 9 + tap];
        v = (w > 0.0f) ? 0x3C00u : ((w < 0.0f) ? 0xBC00u : 0u);
    }
    *(unsigned short*)&g_wb2[(size_t)tg * 5120 + row * 64 + (((j >> 3) ^ (row & 7)) * 8) + (j & 7)] = v;
}

// ================= conv1: 128px x 192oc per CTA, 256 threads (8 warps 2Mx4N) =================
// it = chunk*9 + tap; B tile index = tap*4 + chunk
// A: halo 264 rows x 128B = 33792B x2 buffers; B: 192x128B = 24576B x4 stages
// Sync cadence: CP_WAIT(0)+__syncthreads only on EVEN iterations.
#define C1_SMEM 165888

__device__ __forceinline__ void c1_agran(uint32_t Ab, int n, int y0, int chunk, int g) {
    int idx = g >> 3, j = g & 7;
    int hy = idx / 66, hx = idx - hy * 66;
    int y = y0 - 1 + hy, x = hx - 1;
    bool ok = ((unsigned)y < 64u) & ((unsigned)x < 64u);
    const char* spk = (const char*)g_spk;
    size_t off = ((((size_t)n * HW) + (size_t)y * 64 + x) * 256 + chunk * 64 + j * 8) * 2;
    CP16(Ab + idx * 128 + (((unsigned)(j ^ (idx & 7))) << 4), ok ? (spk + off) : spk, ok ? 16 : 0);
}

__global__ void __launch_bounds__(256, 1) conv1_kernel() {
    extern __shared__ char sm[];
    uint32_t sb = smem_u32(sm);
    int tid = threadIdx.x, l = tid & 31, wid = tid >> 5;
    int wm = wid & 1, wn = wid >> 1;                 // 2 M-warps x 4 N-warps
    int n = blockIdx.x >> 5, y0 = (blockIdx.x & 31) * 2;

    int mat = l >> 3, mr = l & 7;
    int a_rl = (mat & 1) * 8 + mr, a_kh = mat >> 1;
    int b_nl = (mat >> 1) * 8 + mr, b_kh = mat & 1;

    float acc[4][6][4];
#pragma unroll
    for (int i = 0; i < 4; i++)
#pragma unroll
        for (int jn = 0; jn < 6; jn++)
#pragma unroll
            for (int q = 0; q < 4; q++) acc[i][jn][q] = 0.0f;

    // prologue: A(chunk0), B(it=0 -> tile 0), B(it=1 -> tile 4)
#pragma unroll
    for (int ii = 0; ii < 9; ii++) {
        int g = tid + ii * 256;
        if (g < 2112) c1_agran(sb, n, y0, 0, g);
    }
#pragma unroll
    for (int s = 0; s < 2; s++) {
        const char* wb = (const char*)g_wb1 + (size_t)(s * 4) * 24576;
        uint32_t Bb = sb + 67584u + (uint32_t)s * 24576u;
#pragma unroll
        for (int ii = 0; ii < 6; ii++) {
            int lin = tid + ii * 256;
            CP16(Bb + lin * 16, wb + lin * 16, 16);
        }
    }
    CP_COMMIT();

    int tap = 0, c = 0;          // decomposition of it
    int tap2 = 2, c2 = 0;        // decomposition of it+2
    for (int it = 0; it < 36; it++) {
        if ((it & 1) == 0) {     // sync point every 2 iterations
            CP_WAIT(0);
            __syncthreads();
        }
        if (it < 34) {
            const char* wb = (const char*)g_wb1 + (size_t)(tap2 * 4 + c2) * 24576;
            uint32_t Bb = sb + 67584u + (uint32_t)((it + 2) & 3) * 24576u;
#pragma unroll
            for (int ii = 0; ii < 6; ii++) {
                int lin = tid + ii * 256;
                CP16(Bb + lin * 16, wb + lin * 16, 16);
            }
        }
        if (tap >= 1 && tap <= 6 && c < 3) {
            uint32_t Ab = sb + (uint32_t)((c + 1) & 1) * 33792u;
            int g0 = (tap - 1) * 352 + tid;
            c1_agran(Ab, n, y0, c + 1, g0);
            if (tid < 96) c1_agran(Ab, n, y0, c + 1, g0 + 256);
        }
        CP_COMMIT();

        uint32_t Ahb = sb + (uint32_t)(c & 1) * 33792u;
        uint32_t Bb = sb + 67584u + (uint32_t)(it & 3) * 24576u;
        int ky = tap / 3, kx = tap - ky * 3;
        int aib = (wm + ky) * 66 + kx + a_rl;
#pragma unroll
        for (int ks = 0; ks < 4; ks++) {
            uint32_t a[4][4];
#pragma unroll
            for (int mt = 0; mt < 4; mt++) {
                int idx = aib + mt * 16;
                uint32_t ad = Ahb + (uint32_t)(idx * 128 + ((((ks << 1) + a_kh) ^ (idx & 7)) << 4));
                LDSM4(a[mt][0], a[mt][1], a[mt][2], a[mt][3], ad);
            }
#pragma unroll
            for (int p = 0; p < 3; p++) {
                int row = wn * 48 + p * 16 + b_nl;
                uint32_t bd = Bb + (uint32_t)(row * 128 + ((((ks << 1) + b_kh) ^ (row & 7)) << 4));
                uint32_t b0, b1, b2, b3;
                LDSM4(b0, b1, b2, b3, bd);
#pragma unroll
                for (int mt = 0; mt < 4; mt++) {
                    MMA(acc[mt][p * 2],     a[mt], b0, b1);
                    MMA(acc[mt][p * 2 + 1], a[mt], b2, b3);
                }
            }
        }
        if (++tap == 9) { tap = 0; c++; }
        if (++tap2 == 9) { tap2 = 0; c2++; }
    }
    // epilogue: NHWC f32 stores + fused BN partials
    float lsum[12], lsq[12];
#pragma unroll
    for (int j = 0; j < 12; j++) { lsum[j] = 0.0f; lsq[j] = 0.0f; }

    size_t pixbase = (size_t)n * HW + (size_t)y0 * 64;
    int c0 = wn * 48 + (l & 3) * 2;
#pragma unroll
    for (int mt = 0; mt < 4; mt++) {
        size_t row = pixbase + wm * 64 + mt * 16 + (l >> 2);
#pragma unroll
        for (int p = 0; p < 6; p++) {
            float* d = acc[mt][p];
#pragma unroll
            for (int q = 0; q < 4; q++) {
                float v = d[q];
                int j = p * 2 + (q & 1);
                lsum[j] += v; lsq[j] += v * v;
            }
            int col = c0 + p * 8;
            *(float2*)&g_y[row * 192 + col]       = make_float2(d[0], d[1]);
            *(float2*)&g_y[(row + 8) * 192 + col] = make_float2(d[2], d[3]);
        }
    }
    // deterministic cross-thread reduction of BN partials (oc-major)
    __syncthreads();
    float* ssum = (float*)sm;                 // 256*12 floats
    float* ssq  = (float*)(sm + 16384);
#pragma unroll
    for (int j = 0; j < 12; j++) { ssum[tid * 12 + j] = lsum[j]; ssq[tid * 12 + j] = lsq[j]; }
    __syncthreads();
    if (tid < 192) {
        int wn_ = tid / 48, r = tid % 48;
        int p = r >> 3, l2 = (r & 7) >> 1, cp = r & 1;
        int j = p * 2 + cp;
        float s = 0.0f, q = 0.0f;
#pragma unroll
        for (int wm_ = 0; wm_ < 2; wm_++)
#pragma unroll
            for (int lr = 0; lr < 8; lr++) {
                int ct = ((wn_ * 2 + wm_) * 32 + lr * 4 + l2) * 12 + j;
                s += ssum[ct]; q += ssq[ct];
            }
        g_p1[blockIdx.x * 192 + tid] = s;
        g_p2[blockIdx.x * 192 + tid] = q;
    }
}

// ---------------- BN finalize (reads 1024 per-CTA partials, fixed order) ----------------
__global__ void bn_final_kernel(const float* __restrict__ gamma, const float* __restrict__ beta) {
    int c = blockIdx.x, t = threadIdx.x;
    float s = 0, q = 0;
    for (int i = t; i < 1024; i += 64) { s += g_p1[i * 192 + c]; q += g_p2[i * 192 + c]; }
    __shared__ float ss[64], sq[64];
    ss[t] = s; sq[t] = q; __syncthreads();
    for (int o = 32; o > 0; o >>= 1) {
        if (t < o) { ss[t] += ss[t + o]; sq[t] += sq[t + o]; }
        __syncthreads();
    }
    if (t == 0) {
        float m = ss[0] / 131072.0f;
        float var = sq[0] / 131072.0f - m * m;
        float sc = rsqrtf(var + 1e-5f) * gamma[c];
        g_scale[c] = sc; g_shift[c] = beta[c] - m * sc;
    }
}

// ---------------- BN apply: x1 (NCHW out) + g_ybh (padded NHWC fp16) ----------------
__global__ void __launch_bounds__(256) bn_apply_kernel(float* __restrict__ out) {
    __shared__ float smt[192 * 33];
    int n = blockIdx.y, px0 = blockIdx.x * 32;
    for (int i = threadIdx.x; i < 32 * 256; i += 256) {
        int pl = i >> 8, cp = i & 255;
        int g = cp >> 6, sft = cp & 63;
        size_t pix = (size_t)n * HW + px0 + pl;
        float r = 0.0f;
        if (sft < 48) {
            int c = g * 48 + sft;
            float v = g_y[pix * 192 + c];
            r = v * g_scale[c] + g_shift[c];
            smt[c * 33 + pl] = r;
        }
        g_ybh[pix * 256 + cp] = __float2half(r);
    }
    __syncthreads();
    for (int j = threadIdx.x; j < 192 * 32; j += 256) {
        int c = j >> 5, pl = j & 31;
        out[((size_t)n * 512 + c) * HW + px0 + pl] = smt[c * 33 + pl];
    }
}

// ================= conv2: 128px x 80oc per CTA (one group) =================
// Channels 48-63 of each group are exact zeros (both A and B) -> ks loops 0..2 only.
// A: halo tile 264 x 128B = 33792B (single buffer, 9 taps share it)
// B: 80 x 128B = 10240B, 4 stages; sync every 2 iterations.
#define C2_SMEM 74752

__device__ __forceinline__ void c2_agran(uint32_t Ab, int n, int y0, int grp, int g) {
    int idx = g >> 3, j = g & 7;
    int hy = idx / 66, hx = idx - hy * 66;
    int y = y0 - 1 + hy, x = hx - 1;
    bool ok = ((unsigned)y < 64u) & ((unsigned)x < 64u);
    const char* src = (const char*)g_ybh;
    size_t off = ((((size_t)n * HW) + (size_t)y * 64 + x) * 256 + grp * 64 + j * 8) * 2;
    CP16(Ab + idx * 128 + (((unsigned)(j ^ (idx & 7))) << 4), ok ? (src + off) : src, ok ? 16 : 0);
}

__global__ void __launch_bounds__(128, 3) conv2_kernel(float* __restrict__ out) {
    extern __shared__ char sm[];
    uint32_t sb = smem_u32(sm);
    int tid = threadIdx.x, l = tid & 31, wm = tid >> 5;   // 4 M-warps
    int g = blockIdx.x & 3, y0 = ((blockIdx.x >> 2) & 31) * 2, n = blockIdx.x >> 7;

    int mat = l >> 3, mr = l & 7;
    int a_rl = (mat & 1) * 8 + mr, a_kh = mat >> 1;
    int b_nl = (mat >> 1) * 8 + mr, b_kh = mat & 1;

    float acc[2][10][4];
#pragma unroll
    for (int i = 0; i < 2; i++)
#pragma unroll
        for (int jn = 0; jn < 10; jn++)
#pragma unroll
            for (int q = 0; q < 4; q++) acc[i][jn][q] = 0.0f;

    // prologue: A halo + B(0) + B(1) in one commit group
#pragma unroll
    for (int ii = 0; ii < 17; ii++) {
        int gg = tid + ii * 128;
        if (gg < 2112) c2_agran(sb, n, y0, g, gg);
    }
#pragma unroll
    for (int s = 0; s < 2; s++) {
        const char* wb = (const char*)g_wb2 + (size_t)(s * 4 + g) * 10240;
        uint32_t Bb = sb + 33792u + (uint32_t)s * 10240u;
#pragma unroll
        for (int ii = 0; ii < 5; ii++) {
            int lin = tid + ii * 128;
            CP16(Bb + lin * 16, wb + lin * 16, 16);
        }
    }
    CP_COMMIT();

    int ry = wm >> 1, rx = (wm & 1) * 32;
    for (int it = 0; it < 9; it++) {
        if ((it & 1) == 0) {       // sync every 2 iterations
            CP_WAIT(0);
            __syncthreads();
        }
        if (it < 7) {
            const char* wb = (const char*)g_wb2 + (size_t)((it + 2) * 4 + g) * 10240;
            uint32_t Bb = sb + 33792u + (uint32_t)((it + 2) & 3) * 10240u;
#pragma unroll
            for (int ii = 0; ii < 5; ii++) {
                int lin = tid + ii * 128;
                CP16(Bb + lin * 16, wb + lin * 16, 16);
            }
        }
        CP_COMMIT();

        uint32_t Bb = sb + 33792u + (uint32_t)(it & 3) * 10240u;
        int ky = it / 3, kx = it - ky * 3;
        int aib = (ry + ky) * 66 + kx + rx + a_rl;
#pragma unroll
        for (int ks = 0; ks < 3; ks++) {   // ks=3 is all zeros (padded channels) -> skipped
            uint32_t a[2][4];
#pragma unroll
            for (int mt = 0; mt < 2; mt++) {
                int idx = aib + mt * 16;
                uint32_t ad = sb + (uint32_t)(idx * 128 + ((((ks << 1) + a_kh) ^ (idx & 7)) << 4));
                LDSM4(a[mt][0], a[mt][1], a[mt][2], a[mt][3], ad);
            }
#pragma unroll
            for (int p = 0; p < 5; p++) {
                int row = p * 16 + b_nl;
                uint32_t bd = Bb + (uint32_t)(row * 128 + ((((ks << 1) + b_kh) ^ (row & 7)) << 4));
                uint32_t b0, b1, b2, b3;
                LDSM4(b0, b1, b2, b3, bd);
#pragma unroll
                for (int mt = 0; mt < 2; mt++) {
                    MMA(acc[mt][p * 2],     a[mt], b0, b1);
                    MMA(acc[mt][p * 2 + 1], a[mt], b2, b3);
                }
            }
        }
    }
    // epilogue: NCHW stores into x2 slice (8-consecutive-row fragments = full sectors)
    float* ob = out + ((size_t)n * 512 + 192 + (size_t)g * 80) * HW + (size_t)y0 * 64;
    int r0 = wm * 32 + (l >> 2), c0 = (l & 3) * 2;
#pragma unroll
    for (int mt = 0; mt < 2; mt++)
#pragma unroll
        for (int nt = 0; nt < 10; nt++) {
            float* d = acc[mt][nt];
            int row = r0 + mt * 16, col = c0 + nt * 8;
            ob[(size_t)col * HW + row]           = d[0];
            ob[(size_t)(col + 1) * HW + row]     = d[1];
            ob[(size_t)col * HW + row + 8]       = d[2];
            ob[(size_t)(col + 1) * HW + row + 8] = d[3];
        }
}

// ---------------- launch ----------------
extern "C" void kernel_launch(void* const* d_in, const int* in_sizes, int n_in,
                              void* d_out, int out_size) {
    const float* x     = (const float*)d_in[0];
    const float* w1    = (const float*)d_in[1];
    const float* gamma = (const float*)d_in[2];
    const float* beta  = (const float*)d_in[3];
    const float* w2    = (const float*)d_in[4];
    float* out = (float*)d_out;

    cudaFuncSetAttribute(conv1_kernel, cudaFuncAttributeMaxDynamicSharedMemorySize, C1_SMEM);
    cudaFuncSetAttribute(conv2_kernel, cudaFuncAttributeMaxDynamicSharedMemorySize, C2_SMEM);

    lif_kernel  <<<dim3(16, 4, 8), 256>>>(x);
    prep1_kernel<<<1728, 256>>>(w1);
    prep2_kernel<<<720, 256>>>(w2);

    conv1_kernel<<<1024, 256, C1_SMEM>>>();   // writes g_y + BN partials

    bn_final_kernel<<<192, 64>>>(gamma, beta);
    bn_apply_kernel<<<dim3(128, 32), 256>>>(out);

    conv2_kernel<<<4096, 128, C2_SMEM>>>(out);
}

// round 14
// speedup vs baseline: 1.0844x; 1.0100x over previous
#include <cuda_runtime.h>
#include <cuda_fp16.h>
#include <cstdint>

#define NNI 32
#define HW  4096

// ---------------- scratch ----------------
__device__ __align__(128) __half g_spk[(size_t)NNI * HW * 256];   // spikes NHWC fp16
__device__ __align__(128) float  g_y  [(size_t)NNI * HW * 192];   // conv1 out NHWC f32
__device__ __align__(128) __half g_ybh[(size_t)NNI * HW * 256];   // BN out fp16 (4x64 padded, ch48-63=0)
__device__ __align__(128) __half g_wb1[36 * 192 * 64];            // [tap*4+chunk][192][64] swizzled
__device__ __align__(128) __half g_wb2[36 * 80 * 64];             // [tap*4+g][80][64] sign, swizzled
__device__ float g_p1[1024 * 192], g_p2[1024 * 192];              // per-conv1-CTA BN partials
__device__ float g_scale[192], g_shift[192];

// ---------------- PTX helpers (sm_80-compatible only) ----------------
__device__ __forceinline__ uint32_t smem_u32(const void* p) {
    uint32_t a;
    asm("{ .reg .u64 t; cvta.to.shared.u64 t, %1; cvt.u32.u64 %0, t; }" : "=r"(a) : "l"(p));
    return a;
}
#define CP16(dst, src, nb) asm volatile("cp.async.cg.shared.global [%0], [%1], 16, %2;" :: "r"(dst), "l"(src), "r"(nb) : "memory")
#define CP_COMMIT() asm volatile("cp.async.commit_group;" ::: "memory")
#define CP_WAIT(n)  asm volatile("cp.async.wait_group %0;" :: "n"(n) : "memory")

#define LDSM4(r0, r1, r2, r3, addr) \
    asm volatile("ldmatrix.sync.aligned.m8n8.x4.shared.b16 {%0,%1,%2,%3}, [%4];" \
        : "=r"(r0), "=r"(r1), "=r"(r2), "=r"(r3) : "r"(addr))

#define MMA(d, a, b0_, b1_) \
    asm volatile("mma.sync.aligned.m16n8k16.row.col.f32.f16.f16.f32 " \
        "{%0,%1,%2,%3}, {%4,%5,%6,%7}, {%8,%9}, {%0,%1,%2,%3};" \
        : "+f"((d)[0]), "+f"((d)[1]), "+f"((d)[2]), "+f"((d)[3]) \
        : "r"((a)[0]), "r"((a)[1]), "r"((a)[2]), "r"((a)[3]), "r"(b0_), "r"(b1_))

// ---------------- LIF -> spikes NHWC fp16 (64ch/thread: 128B full-line stores) ----------------
__global__ void __launch_bounds__(256) lif_kernel(const float* __restrict__ x) {
    int px = blockIdx.x * 256 + threadIdx.x;
    int cc0 = blockIdx.y * 64, b = blockIdx.z;
    float v[64];
#pragma unroll
    for (int c = 0; c < 64; c++) v[c] = 0.0f;
#pragma unroll
    for (int t = 0; t < 4; t++) {
        const float* xp = x + ((size_t)(t * 8 + b) * 256 + cc0) * HW + px;
        uint4* dst = (uint4*)(g_spk + ((size_t)(t * 8 + b) * HW + px) * 256 + cc0);
#pragma unroll
        for (int q = 0; q < 8; q++) {
            unsigned pk[4];
#pragma unroll
            for (int cc = 0; cc < 8; cc++) {
                int c = q * 8 + cc;
                float xv = xp[(size_t)c * HW];
                float nv = v[c] + (xv - v[c]) * 0.5f;
                unsigned s = (nv >= 1.0f) ? 0x3C00u : 0u;
                v[c] = nv - ((nv >= 1.0f) ? 1.0f : 0.0f);
                if (cc & 1) pk[cc >> 1] |= (s << 16); else pk[cc >> 1] = s;
            }
            dst[q] = make_uint4(pk[0], pk[1], pk[2], pk[3]);
        }
    }
}

// ---------------- weight prep (pre-swizzled gmem tiles) ----------------
__global__ void prep1_kernel(const float* __restrict__ w1) {
    int i = blockIdx.x * 256 + threadIdx.x;           // 36*192*64
    if (i >= 36 * 192 * 64) return;
    int j = i & 63, row = (i >> 6) % 192, it = (i >> 6) / 192;
    int tap = it >> 2, c = (it & 3) * 64 + j;
    float w = w1[((size_t)row * 256 + c) * 9 + tap];
    g_wb1[(size_t)it * 12288 + row * 64 + (((j >> 3) ^ (row & 7)) * 8) + (j & 7)] = __float2half(w);
}
__global__ void prep2_kernel(const float* __restrict__ w2) {
    int i = blockIdx.x * 256 + threadIdx.x;           // 36*80*64
    if (i >= 36 * 80 * 64) return;
    int j = i & 63, row = (i >> 6) % 80, tg = (i >> 6) / 80;
    int g = tg & 3, tap = tg >> 2;
    unsigned short v = 0;
    if (j < 48) {
        float w = w2[(((size_t)(g * 80 + row)) * 48 + j) * 9 + tap];
        v = (w > 0.0f) ? 0x3C00u : ((w < 0.0f) ? 0xBC00u : 0u);
    }
    *(unsigned short*)&g_wb2[(size_t)tg * 5120 + row * 64 + (((j >> 3) ^ (row & 7)) * 8) + (j & 7)] = v;
}

// ================= conv1: 128px x 192oc per CTA, 256 threads (8 warps 2Mx4N) =================
// it = chunk*9 + tap; B tile index = tap*4 + chunk
// A: halo 264 rows x 128B = 33792B x2 buffers; B: 192x128B = 24576B x6 stages
// Barriers every 3 its (CP_WAIT(0)); B prefetch distance 4; A prefetch spread taps 1..5.
#define C1_SMEM 215040

__device__ __forceinline__ void c1_agran(uint32_t Ab, int n, int y0, int chunk, int g) {
    int idx = g >> 3, j = g & 7;
    int hy = idx / 66, hx = idx - hy * 66;
    int y = y0 - 1 + hy, x = hx - 1;
    bool ok = ((unsigned)y < 64u) & ((unsigned)x < 64u);
    const char* spk = (const char*)g_spk;
    size_t off = ((((size_t)n * HW) + (size_t)y * 64 + x) * 256 + chunk * 64 + j * 8) * 2;
    CP16(Ab + idx * 128 + (((unsigned)(j ^ (idx & 7))) << 4), ok ? (spk + off) : spk, ok ? 16 : 0);
}

__global__ void __launch_bounds__(256, 1) conv1_kernel() {
    extern __shared__ char sm[];
    uint32_t sb = smem_u32(sm);
    int tid = threadIdx.x, l = tid & 31, wid = tid >> 5;
    int wm = wid & 1, wn = wid >> 1;                 // 2 M-warps x 4 N-warps
    int n = blockIdx.x >> 5, y0 = (blockIdx.x & 31) * 2;

    int mat = l >> 3, mr = l & 7;
    int a_rl = (mat & 1) * 8 + mr, a_kh = mat >> 1;
    int b_nl = (mat >> 1) * 8 + mr, b_kh = mat & 1;

    float acc[4][6][4];
#pragma unroll
    for (int i = 0; i < 4; i++)
#pragma unroll
        for (int jn = 0; jn < 6; jn++)
#pragma unroll
            for (int q = 0; q < 4; q++) acc[i][jn][q] = 0.0f;

    // prologue: A(chunk0) + B tiles for it=0..3 (tile index = tap*4, tap=it since chunk=0)
#pragma unroll
    for (int ii = 0; ii < 9; ii++) {
        int g = tid + ii * 256;
        if (g < 2112) c1_agran(sb, n, y0, 0, g);
    }
#pragma unroll
    for (int s = 0; s < 4; s++) {
        const char* wb = (const char*)g_wb1 + (size_t)(s * 4) * 24576;
        uint32_t Bb = sb + 67584u + (uint32_t)s * 24576u;
#pragma unroll
        for (int ii = 0; ii < 6; ii++) {
            int lin = tid + ii * 256;
            CP16(Bb + lin * 16, wb + lin * 16, 16);
        }
    }
    CP_COMMIT();

    int tap = 0, c = 0;            // decomposition of it
    int tap4 = 4, c4 = 0;          // decomposition of it+4
    int bs = 0, bs4 = 4;           // B stage of it, it+4 (mod 6)
    int sc = 0;                    // sync cadence counter (mod 3)
    for (int it = 0; it < 36; it++) {
        if (sc == 0) {             // sync point every 3 iterations
            CP_WAIT(0);
            __syncthreads();
        }
        // prefetch B(it+4)
        if (it < 32) {
            const char* wb = (const char*)g_wb1 + (size_t)(tap4 * 4 + c4) * 24576;
            uint32_t Bb = sb + 67584u + (uint32_t)bs4 * 24576u;
#pragma unroll
            for (int ii = 0; ii < 6; ii++) {
                int lin = tid + ii * 256;
                CP16(Bb + lin * 16, wb + lin * 16, 16);
            }
        }
        // prefetch A(c+1) spread over taps 1..5 (423 granules per tap)
        if (tap >= 1 && tap <= 5 && c < 3) {
            uint32_t Ab = sb + (uint32_t)((c + 1) & 1) * 33792u;
            int g0 = (tap - 1) * 423 + tid;
            if (g0 < 2112) c1_agran(Ab, n, y0, c + 1, g0);
            if (tid < 167 && g0 + 256 < 2112) c1_agran(Ab, n, y0, c + 1, g0 + 256);
        }
        CP_COMMIT();

        uint32_t Ahb = sb + (uint32_t)(c & 1) * 33792u;
        uint32_t Bb = sb + 67584u + (uint32_t)bs * 24576u;
        int ky = tap / 3, kx = tap - ky * 3;
        int aib = (wm + ky) * 66 + kx + a_rl;
#pragma unroll
        for (int ks = 0; ks < 4; ks++) {
            uint32_t a[4][4];
#pragma unroll
            for (int mt = 0; mt < 4; mt++) {
                int idx = aib + mt * 16;
                uint32_t ad = Ahb + (uint32_t)(idx * 128 + ((((ks << 1) + a_kh) ^ (idx & 7)) << 4));
                LDSM4(a[mt][0], a[mt][1], a[mt][2], a[mt][3], ad);
            }
#pragma unroll
            for (int p = 0; p < 3; p++) {
                int row = wn * 48 + p * 16 + b_nl;
                uint32_t bd = Bb + (uint32_t)(row * 128 + ((((ks << 1) + b_kh) ^ (row & 7)) << 4));
                uint32_t b0, b1, b2, b3;
                LDSM4(b0, b1, b2, b3, bd);
#pragma unroll
                for (int mt = 0; mt < 4; mt++) {
                    MMA(acc[mt][p * 2],     a[mt], b0, b1);
                    MMA(acc[mt][p * 2 + 1], a[mt], b2, b3);
                }
            }
        }
        if (++tap == 9) { tap = 0; c++; }
        if (++tap4 == 9) { tap4 = 0; c4++; }
        bs = (bs + 1 == 6) ? 0 : bs + 1;
        bs4 = (bs4 + 1 == 6) ? 0 : bs4 + 1;
        sc = (sc + 1 == 3) ? 0 : sc + 1;
    }
    // epilogue: NHWC f32 stores + fused BN partials
    float lsum[12], lsq[12];
#pragma unroll
    for (int j = 0; j < 12; j++) { lsum[j] = 0.0f; lsq[j] = 0.0f; }

    size_t pixbase = (size_t)n * HW + (size_t)y0 * 64;
    int c0 = wn * 48 + (l & 3) * 2;
#pragma unroll
    for (int mt = 0; mt < 4; mt++) {
        size_t row = pixbase + wm * 64 + mt * 16 + (l >> 2);
#pragma unroll
        for (int p = 0; p < 6; p++) {
            float* d = acc[mt][p];
#pragma unroll
            for (int q = 0; q < 4; q++) {
                float v = d[q];
                int j = p * 2 + (q & 1);
                lsum[j] += v; lsq[j] += v * v;
            }
            int col = c0 + p * 8;
            *(float2*)&g_y[row * 192 + col]       = make_float2(d[0], d[1]);
            *(float2*)&g_y[(row + 8) * 192 + col] = make_float2(d[2], d[3]);
        }
    }
    // deterministic cross-thread reduction of BN partials (oc-major)
    __syncthreads();
    float* ssum = (float*)sm;                 // 256*12 floats
    float* ssq  = (float*)(sm + 16384);
#pragma unroll
    for (int j = 0; j < 12; j++) { ssum[tid * 12 + j] = lsum[j]; ssq[tid * 12 + j] = lsq[j]; }
    __syncthreads();
    if (tid < 192) {
        int wn_ = tid / 48, r = tid % 48;
        int p = r >> 3, l2 = (r & 7) >> 1, cp = r & 1;
        int j = p * 2 + cp;
        float s = 0.0f, q = 0.0f;
#pragma unroll
        for (int wm_ = 0; wm_ < 2; wm_++)
#pragma unroll
            for (int lr = 0; lr < 8; lr++) {
                int ct = ((wn_ * 2 + wm_) * 32 + lr * 4 + l2) * 12 + j;
                s += ssum[ct]; q += ssq[ct];
            }
        g_p1[blockIdx.x * 192 + tid] = s;
        g_p2[blockIdx.x * 192 + tid] = q;
    }
}

// ---------------- BN finalize (reads 1024 per-CTA partials, fixed order) ----------------
__global__ void bn_final_kernel(const float* __restrict__ gamma, const float* __restrict__ beta) {
    int c = blockIdx.x, t = threadIdx.x;
    float s = 0, q = 0;
    for (int i = t; i < 1024; i += 64) { s += g_p1[i * 192 + c]; q += g_p2[i * 192 + c]; }
    __shared__ float ss[64], sq[64];
    ss[t] = s; sq[t] = q; __syncthreads();
    for (int o = 32; o > 0; o >>= 1) {
        if (t < o) { ss[t] += ss[t + o]; sq[t] += sq[t + o]; }
        __syncthreads();
    }
    if (t == 0) {
        float m = ss[0] / 131072.0f;
        float var = sq[0] / 131072.0f - m * m;
        float sc = rsqrtf(var + 1e-5f) * gamma[c];
        g_scale[c] = sc; g_shift[c] = beta[c] - m * sc;
    }
}

// ---------------- BN apply: x1 (NCHW out) + g_ybh (padded NHWC fp16) ----------------
__global__ void __launch_bounds__(256) bn_apply_kernel(float* __restrict__ out) {
    __shared__ float smt[192 * 33];
    int n = blockIdx.y, px0 = blockIdx.x * 32;
    for (int i = threadIdx.x; i < 32 * 256; i += 256) {
        int pl = i >> 8, cp = i & 255;
        int g = cp >> 6, sft = cp & 63;
        size_t pix = (size_t)n * HW + px0 + pl;
        float r = 0.0f;
        if (sft < 48) {
            int c = g * 48 + sft;
            float v = g_y[pix * 192 + c];
            r = v * g_scale[c] + g_shift[c];
            smt[c * 33 + pl] = r;
        }
        g_ybh[pix * 256 + cp] = __float2half(r);
    }
    __syncthreads();
    for (int j = threadIdx.x; j < 192 * 32; j += 256) {
        int c = j >> 5, pl = j & 31;
        out[((size_t)n * 512 + c) * HW + px0 + pl] = smt[c * 33 + pl];
    }
}

// ================= conv2: 128px x 80oc per CTA (one group) =================
// Channels 48-63 of each group are exact zeros (both A and B) -> ks loops 0..2 only.
// A: halo tile 264 x 128B = 33792B (single buffer, 9 taps share it)
// B: 80 x 128B = 10240B, 4 stages; sync every 2 iterations.
#define C2_SMEM 74752

__device__ __forceinline__ void c2_agran(uint32_t Ab, int n, int y0, int grp, int g) {
    int idx = g >> 3, j = g & 7;
    int hy = idx / 66, hx = idx - hy * 66;
    int y = y0 - 1 + hy, x = hx - 1;
    bool ok = ((unsigned)y < 64u) & ((unsigned)x < 64u);
    const char* src = (const char*)g_ybh;
    size_t off = ((((size_t)n * HW) + (size_t)y * 64 + x) * 256 + grp * 64 + j * 8) * 2;
    CP16(Ab + idx * 128 + (((unsigned)(j ^ (idx & 7))) << 4), ok ? (src + off) : src, ok ? 16 : 0);
}

__global__ void __launch_bounds__(128, 3) conv2_kernel(float* __restrict__ out) {
    extern __shared__ char sm[];
    uint32_t sb = smem_u32(sm);
    int tid = threadIdx.x, l = tid & 31, wm = tid >> 5;   // 4 M-warps
    int g = blockIdx.x & 3, y0 = ((blockIdx.x >> 2) & 31) * 2, n = blockIdx.x >> 7;

    int mat = l >> 3, mr = l & 7;
    int a_rl = (mat & 1) * 8 + mr, a_kh = mat >> 1;
    int b_nl = (mat >> 1) * 8 + mr, b_kh = mat & 1;

    float acc[2][10][4];
#pragma unroll
    for (int i = 0; i < 2; i++)
#pragma unroll
        for (int jn = 0; jn < 10; jn++)
#pragma unroll
            for (int q = 0; q < 4; q++) acc[i][jn][q] = 0.0f;

    // prologue: A halo + B(0) + B(1) in one commit group
#pragma unroll
    for (int ii = 0; ii < 17; ii++) {
        int gg = tid + ii * 128;
        if (gg < 2112) c2_agran(sb, n, y0, g, gg);
    }
#pragma unroll
    for (int s = 0; s < 2; s++) {
        const char* wb = (const char*)g_wb2 + (size_t)(s * 4 + g) * 10240;
        uint32_t Bb = sb + 33792u + (uint32_t)s * 10240u;
#pragma unroll
        for (int ii = 0; ii < 5; ii++) {
            int lin = tid + ii * 128;
            CP16(Bb + lin * 16, wb + lin * 16, 16);
        }
    }
    CP_COMMIT();

    int ry = wm >> 1, rx = (wm & 1) * 32;
    for (int it = 0; it < 9; it++) {
        if ((it & 1) == 0) {       // sync every 2 iterations
            CP_WAIT(0);
            __syncthreads();
        }
        if (it < 7) {
            const char* wb = (const char*)g_wb2 + (size_t)((it + 2) * 4 + g) * 10240;
            uint32_t Bb = sb + 33792u + (uint32_t)((it + 2) & 3) * 10240u;
#pragma unroll
            for (int ii = 0; ii < 5; ii++) {
                int lin = tid + ii * 128;
                CP16(Bb + lin * 16, wb + lin * 16, 16);
            }
        }
        CP_COMMIT();

        uint32_t Bb = sb + 33792u + (uint32_t)(it & 3) * 10240u;
        int ky = it / 3, kx = it - ky * 3;
        int aib = (ry + ky) * 66 + kx + rx + a_rl;
#pragma unroll
        for (int ks = 0; ks < 3; ks++) {   // ks=3 is all zeros (padded channels) -> skipped
            uint32_t a[2][4];
#pragma unroll
            for (int mt = 0; mt < 2; mt++) {
                int idx = aib + mt * 16;
                uint32_t ad = sb + (uint32_t)(idx * 128 + ((((ks << 1) + a_kh) ^ (idx & 7)) << 4));
                LDSM4(a[mt][0], a[mt][1], a[mt][2], a[mt][3], ad);
            }
#pragma unroll
            for (int p = 0; p < 5; p++) {
                int row = p * 16 + b_nl;
                uint32_t bd = Bb + (uint32_t)(row * 128 + ((((ks << 1) + b_kh) ^ (row & 7)) << 4));
                uint32_t b0, b1, b2, b3;
                LDSM4(b0, b1, b2, b3, bd);
#pragma unroll
                for (int mt = 0; mt < 2; mt++) {
                    MMA(acc[mt][p * 2],     a[mt], b0, b1);
                    MMA(acc[mt][p * 2 + 1], a[mt], b2, b3);
                }
            }
        }
    }
    // epilogue: NCHW stores into x2 slice (8-consecutive-row fragments = full sectors)
    float* ob = out + ((size_t)n * 512 + 192 + (size_t)g * 80) * HW + (size_t)y0 * 64;
    int r0 = wm * 32 + (l >> 2), c0 = (l & 3) * 2;
#pragma unroll
    for (int mt = 0; mt < 2; mt++)
#pragma unroll
        for (int nt = 0; nt < 10; nt++) {
            float* d = acc[mt][nt];
            int row = r0 + mt * 16, col = c0 + nt * 8;
            ob[(size_t)col * HW + row]           = d[0];
            ob[(size_t)(col + 1) * HW + row]     = d[1];
            ob[(size_t)col * HW + row + 8]       = d[2];
            ob[(size_t)(col + 1) * HW + row + 8] = d[3];
        }
}

// ---------------- launch ----------------
extern "C" void kernel_launch(void* const* d_in, const int* in_sizes, int n_in,
                              void* d_out, int out_size) {
    const float* x     = (const float*)d_in[0];
    const float* w1    = (const float*)d_in[1];
    const float* gamma = (const float*)d_in[2];
    const float* beta  = (const float*)d_in[3];
    const float* w2    = (const float*)d_in[4];
    float* out = (float*)d_out;

    cudaFuncSetAttribute(conv1_kernel, cudaFuncAttributeMaxDynamicSharedMemorySize, C1_SMEM);
    cudaFuncSetAttribute(conv2_kernel, cudaFuncAttributeMaxDynamicSharedMemorySize, C2_SMEM);

    lif_kernel  <<<dim3(16, 4, 8), 256>>>(x);
    prep1_kernel<<<1728, 256>>>(w1);
    prep2_kernel<<<720, 256>>>(w2);

    conv1_kernel<<<1024, 256, C1_SMEM>>>();   // writes g_y + BN partials

    bn_final_kernel<<<192, 64>>>(gamma, beta);
    bn_apply_kernel<<<dim3(128, 32), 256>>>(out);

    conv2_kernel<<<4096, 128, C2_SMEM>>>(out);
}

// round 16
// speedup vs baseline: 1.1139x; 1.0272x over previous
#include <cuda_runtime.h>
#include <cuda_fp16.h>
#include <cstdint>

#define NNI 32
#define HW  4096

// ---------------- scratch ----------------
__device__ __align__(128) __half g_spk[(size_t)NNI * HW * 256];   // spikes NHWC fp16
__device__ __align__(128) __half g_y  [(size_t)NNI * HW * 192];   // conv1 out NHWC fp16
__device__ __align__(128) __half g_ybh[(size_t)NNI * HW * 256];   // BN out fp16 (4x64 padded, ch48-63=0)
__device__ __align__(128) __half g_wb1[36 * 192 * 64];            // [tap*4+chunk][192][64] swizzled
__device__ __align__(128) __half g_wb2[36 * 80 * 64];             // [tap*4+g][80][64] sign, swizzled
__device__ float g_p1[1024 * 192], g_p2[1024 * 192];              // per-conv1-CTA BN partials
__device__ float g_scale[192], g_shift[192];

// ---------------- PTX helpers (sm_80-compatible only) ----------------
__device__ __forceinline__ uint32_t smem_u32(const void* p) {
    uint32_t a;
    asm("{ .reg .u64 t; cvta.to.shared.u64 t, %1; cvt.u32.u64 %0, t; }" : "=r"(a) : "l"(p));
    return a;
}
#define CP16(dst, src, nb) asm volatile("cp.async.cg.shared.global [%0], [%1], 16, %2;" :: "r"(dst), "l"(src), "r"(nb) : "memory")
#define CP_COMMIT() asm volatile("cp.async.commit_group;" ::: "memory")
#define CP_WAIT(n)  asm volatile("cp.async.wait_group %0;" :: "n"(n) : "memory")

#define LDSM4(r0, r1, r2, r3, addr) \
    asm volatile("ldmatrix.sync.aligned.m8n8.x4.shared.b16 {%0,%1,%2,%3}, [%4];" \
        : "=r"(r0), "=r"(r1), "=r"(r2), "=r"(r3) : "r"(addr))

#define MMA(d, a, b0_, b1_) \
    asm volatile("mma.sync.aligned.m16n8k16.row.col.f32.f16.f16.f32 " \
        "{%0,%1,%2,%3}, {%4,%5,%6,%7}, {%8,%9}, {%0,%1,%2,%3};" \
        : "+f"((d)[0]), "+f"((d)[1]), "+f"((d)[2]), "+f"((d)[3]) \
        : "r"((a)[0]), "r"((a)[1]), "r"((a)[2]), "r"((a)[3]), "r"(b0_), "r"(b1_))

// ---------------- LIF -> spikes NHWC fp16 (64ch/thread: 128B full-line stores) ----------------
__global__ void __launch_bounds__(256) lif_kernel(const float* __restrict__ x) {
    int px = blockIdx.x * 256 + threadIdx.x;
    int cc0 = blockIdx.y * 64, b = blockIdx.z;
    float v[64];
#pragma unroll
    for (int c = 0; c < 64; c++) v[c] = 0.0f;
#pragma unroll
    for (int t = 0; t < 4; t++) {
        const float* xp = x + ((size_t)(t * 8 + b) * 256 + cc0) * HW + px;
        uint4* dst = (uint4*)(g_spk + ((size_t)(t * 8 + b) * HW + px) * 256 + cc0);
#pragma unroll
        for (int q = 0; q < 8; q++) {
            unsigned pk[4];
#pragma unroll
            for (int cc = 0; cc < 8; cc++) {
                int c = q * 8 + cc;
                float xv = xp[(size_t)c * HW];
                float nv = v[c] + (xv - v[c]) * 0.5f;
                unsigned s = (nv >= 1.0f) ? 0x3C00u : 0u;
                v[c] = nv - ((nv >= 1.0f) ? 1.0f : 0.0f);
                if (cc & 1) pk[cc >> 1] |= (s << 16); else pk[cc >> 1] = s;
            }
            dst[q] = make_uint4(pk[0], pk[1], pk[2], pk[3]);
        }
    }
}

// ---------------- weight prep (pre-swizzled gmem tiles) ----------------
__global__ void prep1_kernel(const float* __restrict__ w1) {
    int i = blockIdx.x * 256 + threadIdx.x;           // 36*192*64
    if (i >= 36 * 192 * 64) return;
    int j = i & 63, row = (i >> 6) % 192, it = (i >> 6) / 192;
    int tap = it >> 2, c = (it & 3) * 64 + j;
    float w = w1[((size_t)row * 256 + c) * 9 + tap];
    g_wb1[(size_t)it * 12288 + row * 64 + (((j >> 3) ^ (row & 7)) * 8) + (j & 7)] = __float2half(w);
}
__global__ void prep2_kernel(const float* __restrict__ w2) {
    int i = blockIdx.x * 256 + threadIdx.x;           // 36*80*64
    if (i >= 36 * 80 * 64) return;
    int j = i & 63, row = (i >> 6) % 80, tg = (i >> 6) / 80;
    int g = tg & 3, tap = tg >> 2;
    unsigned short v = 0;
    if (j < 48) {
        float w = w2[(((size_t)(g * 80 + row)) * 48 + j) * 9 + tap];
        v = (w > 0.0f) ? 0x3C00u : ((w < 0.0f) ? 0xBC00u : 0u);
    }
    *(unsigned short*)&g_wb2[(size_t)tg * 5120 + row * 64 + (((j >> 3) ^ (row & 7)) * 8) + (j & 7)] = v;
}

// ================= conv1: 128px x 192oc per CTA, 256 threads (8 warps 2Mx4N) =================
// it = chunk*9 + tap; B tile index = tap*4 + chunk
// A: halo 264 rows x 128B = 33792B x2 buffers; B: 192x128B = 24576B x6 stages
// Barriers every 3 its (CP_WAIT(1); it=0 uses CP_WAIT(0) to drain the prologue group).
#define C1_SMEM 215040

__device__ __forceinline__ void c1_agran(uint32_t Ab, int n, int y0, int chunk, int g) {
    int idx = g >> 3, j = g & 7;
    int hy = idx / 66, hx = idx - hy * 66;
    int y = y0 - 1 + hy, x = hx - 1;
    bool ok = ((unsigned)y < 64u) & ((unsigned)x < 64u);
    const char* spk = (const char*)g_spk;
    size_t off = ((((size_t)n * HW) + (size_t)y * 64 + x) * 256 + chunk * 64 + j * 8) * 2;
    CP16(Ab + idx * 128 + (((unsigned)(j ^ (idx & 7))) << 4), ok ? (spk + off) : spk, ok ? 16 : 0);
}

__global__ void __launch_bounds__(256, 1) conv1_kernel() {
    extern __shared__ char sm[];
    uint32_t sb = smem_u32(sm);
    int tid = threadIdx.x, l = tid & 31, wid = tid >> 5;
    int wm = wid & 1, wn = wid >> 1;                 // 2 M-warps x 4 N-warps
    int n = blockIdx.x >> 5, y0 = (blockIdx.x & 31) * 2;

    int mat = l >> 3, mr = l & 7;
    int a_rl = (mat & 1) * 8 + mr, a_kh = mat >> 1;
    int b_nl = (mat >> 1) * 8 + mr, b_kh = mat & 1;

    float acc[4][6][4];
#pragma unroll
    for (int i = 0; i < 4; i++)
#pragma unroll
        for (int jn = 0; jn < 6; jn++)
#pragma unroll
            for (int q = 0; q < 4; q++) acc[i][jn][q] = 0.0f;

    // prologue: A(chunk0) + B tiles for it=0..3 (tile index = tap*4, tap=it since chunk=0)
#pragma unroll
    for (int ii = 0; ii < 9; ii++) {
        int g = tid + ii * 256;
        if (g < 2112) c1_agran(sb, n, y0, 0, g);
    }
#pragma unroll
    for (int s = 0; s < 4; s++) {
        const char* wb = (const char*)g_wb1 + (size_t)(s * 4) * 24576;
        uint32_t Bb = sb + 67584u + (uint32_t)s * 24576u;
#pragma unroll
        for (int ii = 0; ii < 6; ii++) {
            int lin = tid + ii * 256;
            CP16(Bb + lin * 16, wb + lin * 16, 16);
        }
    }
    CP_COMMIT();

    int tap = 0, c = 0;            // decomposition of it
    int tap4 = 4, c4 = 0;          // decomposition of it+4
    int bs = 0, bs4 = 4;           // B stage of it, it+4 (mod 6)
    int sc = 0;                    // sync cadence counter (mod 3)
    for (int it = 0; it < 36; it++) {
        if (sc == 0) {             // sync point every 3 iterations
            if (it == 0) CP_WAIT(0);   // prologue group MUST be drained before first reads
            else         CP_WAIT(1);   // newest group (issued it-1) may stay in flight
            __syncthreads();
        }
        // prefetch B(it+4)
        if (it < 32) {
            const char* wb = (const char*)g_wb1 + (size_t)(tap4 * 4 + c4) * 24576;
            uint32_t Bb = sb + 67584u + (uint32_t)bs4 * 24576u;
#pragma unroll
            for (int ii = 0; ii < 6; ii++) {
                int lin = tid + ii * 256;
                CP16(Bb + lin * 16, wb + lin * 16, 16);
            }
        }
        // prefetch A(c+1) spread over taps 1..5 (423 granules per tap)
        if (tap >= 1 && tap <= 5 && c < 3) {
            uint32_t Ab = sb + (uint32_t)((c + 1) & 1) * 33792u;
            int g0 = (tap - 1) * 423 + tid;
            if (g0 < 2112) c1_agran(Ab, n, y0, c + 1, g0);
            if (tid < 167 && g0 + 256 < 2112) c1_agran(Ab, n, y0, c + 1, g0 + 256);
        }
        CP_COMMIT();

        uint32_t Ahb = sb + (uint32_t)(c & 1) * 33792u;
        uint32_t Bb = sb + 67584u + (uint32_t)bs * 24576u;
        int ky = tap / 3, kx = tap - ky * 3;
        int aib = (wm + ky) * 66 + kx + a_rl;
#pragma unroll
        for (int ks = 0; ks < 4; ks++) {
            uint32_t a[4][4];
#pragma unroll
            for (int mt = 0; mt < 4; mt++) {
                int idx = aib + mt * 16;
                uint32_t ad = Ahb + (uint32_t)(idx * 128 + ((((ks << 1) + a_kh) ^ (idx & 7)) << 4));
                LDSM4(a[mt][0], a[mt][1], a[mt][2], a[mt][3], ad);
            }
#pragma unroll
            for (int p = 0; p < 3; p++) {
                int row = wn * 48 + p * 16 + b_nl;
                uint32_t bd = Bb + (uint32_t)(row * 128 + ((((ks << 1) + b_kh) ^ (row & 7)) << 4));
                uint32_t b0, b1, b2, b3;
                LDSM4(b0, b1, b2, b3, bd);
#pragma unroll
                for (int mt = 0; mt < 4; mt++) {
                    MMA(acc[mt][p * 2],     a[mt], b0, b1);
                    MMA(acc[mt][p * 2 + 1], a[mt], b2, b3);
                }
            }
        }
        if (++tap == 9) { tap = 0; c++; }
        if (++tap4 == 9) { tap4 = 0; c4++; }
        bs = (bs + 1 == 6) ? 0 : bs + 1;
        bs4 = (bs4 + 1 == 6) ? 0 : bs4 + 1;
        sc = (sc + 1 == 3) ? 0 : sc + 1;
    }

    // ---- epilogue: BN partials from fp32 accs + fp16 smem-staged coalesced stores ----
    float lsum[12], lsq[12];
#pragma unroll
    for (int j = 0; j < 12; j++) { lsum[j] = 0.0f; lsq[j] = 0.0f; }

    CP_WAIT(0);                               // drain any straggler cp.async before smem reuse
    __syncthreads();                          // all LDSM reads done; reuse smem
    __half* stg = (__half*)sm;                // [128][200] halfs = 51200B
    int c0 = wn * 48 + (l & 3) * 2;
#pragma unroll
    for (int mt = 0; mt < 4; mt++) {
        int px = wm * 64 + mt * 16 + (l >> 2);
#pragma unroll
        for (int p = 0; p < 6; p++) {
            float* d = acc[mt][p];
#pragma unroll
            for (int q = 0; q < 4; q++) {
                float v = d[q];
                int j = p * 2 + (q & 1);
                lsum[j] += v; lsq[j] += v * v;
            }
            int col = c0 + p * 8;
            *(__half2*)&stg[px * 200 + col]       = __floats2half2_rn(d[0], d[1]);
            *(__half2*)&stg[(px + 8) * 200 + col] = __floats2half2_rn(d[2], d[3]);
        }
    }
    __syncthreads();
    size_t pixbase = (size_t)n * HW + (size_t)y0 * 64;
    for (int k = tid; k < 3072; k += 256) {   // 128 px x 24 uint4 (=192 halfs)
        int px = k / 24, j = k % 24;
        uint4 v = *(const uint4*)&stg[px * 200 + j * 8];
        *(uint4*)&g_y[(pixbase + px) * 192 + j * 8] = v;
    }
    // deterministic cross-thread reduction of BN partials (oc-major)
    __syncthreads();
    float* ssum = (float*)sm;                 // 256*12 floats
    float* ssq  = (float*)(sm + 16384);
#pragma unroll
    for (int j = 0; j < 12; j++) { ssum[tid * 12 + j] = lsum[j]; ssq[tid * 12 + j] = lsq[j]; }
    __syncthreads();
    if (tid < 192) {
        int wn_ = tid / 48, r = tid % 48;
        int p = r >> 3, l2 = (r & 7) >> 1, cp = r & 1;
        int j = p * 2 + cp;
        float s = 0.0f, q = 0.0f;
#pragma unroll
        for (int wm_ = 0; wm_ < 2; wm_++)
#pragma unroll
            for (int lr = 0; lr < 8; lr++) {
                int ct = ((wn_ * 2 + wm_) * 32 + lr * 4 + l2) * 12 + j;
                s += ssum[ct]; q += ssq[ct];
            }
        g_p1[blockIdx.x * 192 + tid] = s;
        g_p2[blockIdx.x * 192 + tid] = q;
    }
}

// ---------------- BN finalize (reads 1024 per-CTA partials, fixed order) ----------------
__global__ void bn_final_kernel(const float* __restrict__ gamma, const float* __restrict__ beta) {
    int c = blockIdx.x, t = threadIdx.x;
    float s = 0, q = 0;
    for (int i = t; i < 1024; i += 64) { s += g_p1[i * 192 + c]; q += g_p2[i * 192 + c]; }
    __shared__ float ss[64], sq[64];
    ss[t] = s; sq[t] = q; __syncthreads();
    for (int o = 32; o > 0; o >>= 1) {
        if (t < o) { ss[t] += ss[t + o]; sq[t] += sq[t + o]; }
        __syncthreads();
    }
    if (t == 0) {
        float m = ss[0] / 131072.0f;
        float var = sq[0] / 131072.0f - m * m;
        float sc = rsqrtf(var + 1e-5f) * gamma[c];
        g_scale[c] = sc; g_shift[c] = beta[c] - m * sc;
    }
}

// ---------------- BN apply: x1 (NCHW out) + g_ybh (padded NHWC fp16) ----------------
__global__ void __launch_bounds__(256) bn_apply_kernel(float* __restrict__ out) {
    __shared__ float smt[192 * 33];
    int n = blockIdx.y, px0 = blockIdx.x * 32;
    for (int i = threadIdx.x; i < 32 * 256; i += 256) {
        int pl = i >> 8, cp = i & 255;
        int g = cp >> 6, sft = cp & 63;
        size_t pix = (size_t)n * HW + px0 + pl;
        float r = 0.0f;
        if (sft < 48) {
            int c = g * 48 + sft;
            float v = __half2float(g_y[pix * 192 + c]);
            r = v * g_scale[c] + g_shift[c];
            smt[c * 33 + pl] = r;
        }
        g_ybh[pix * 256 + cp] = __float2half(r);
    }
    __syncthreads();
    for (int j = threadIdx.x; j < 192 * 32; j += 256) {
        int c = j >> 5, pl = j & 31;
        out[((size_t)n * 512 + c) * HW + px0 + pl] = smt[c * 33 + pl];
    }
}

// ================= conv2: 128px x 80oc per CTA (one group) =================
// Channels 48-63 of each group are exact zeros (both A and B) -> ks loops 0..2 only.
// A: halo tile 264 x 128B = 33792B (single buffer, 9 taps share it)
// B: 80 x 128B = 10240B, 4 stages; sync every 2 iterations.
#define C2_SMEM 74752

__device__ __forceinline__ void c2_agran(uint32_t Ab, int n, int y0, int grp, int g) {
    int idx = g >> 3, j = g & 7;
    int hy = idx / 66, hx = idx - hy * 66;
    int y = y0 - 1 + hy, x = hx - 1;
    bool ok = ((unsigned)y < 64u) & ((unsigned)x < 64u);
    const char* src = (const char*)g_ybh;
    size_t off = ((((size_t)n * HW) + (size_t)y * 64 + x) * 256 + grp * 64 + j * 8) * 2;
    CP16(Ab + idx * 128 + (((unsigned)(j ^ (idx & 7))) << 4), ok ? (src + off) : src, ok ? 16 : 0);
}

__global__ void __launch_bounds__(128, 3) conv2_kernel(float* __restrict__ out) {
    extern __shared__ char sm[];
    uint32_t sb = smem_u32(sm);
    int tid = threadIdx.x, l = tid & 31, wm = tid >> 5;   // 4 M-warps
    int g = blockIdx.x & 3, y0 = ((blockIdx.x >> 2) & 31) * 2, n = blockIdx.x >> 7;

    int mat = l >> 3, mr = l & 7;
    int a_rl = (mat & 1) * 8 + mr, a_kh = mat >> 1;
    int b_nl = (mat >> 1) * 8 + mr, b_kh = mat & 1;

    float acc[2][10][4];
#pragma unroll
    for (int i = 0; i < 2; i++)
#pragma unroll
        for (int jn = 0; jn < 10; jn++)
#pragma unroll
            for (int q = 0; q < 4; q++) acc[i][jn][q] = 0.0f;

    // prologue: A halo + B(0) + B(1) in one commit group
#pragma unroll
    for (int ii = 0; ii < 17; ii++) {
        int gg = tid + ii * 128;
        if (gg < 2112) c2_agran(sb, n, y0, g, gg);
    }
#pragma unroll
    for (int s = 0; s < 2; s++) {
        const char* wb = (const char*)g_wb2 + (size_t)(s * 4 + g) * 10240;
        uint32_t Bb = sb + 33792u + (uint32_t)s * 10240u;
#pragma unroll
        for (int ii = 0; ii < 5; ii++) {
            int lin = tid + ii * 128;
            CP16(Bb + lin * 16, wb + lin * 16, 16);
        }
    }
    CP_COMMIT();

    int ry = wm >> 1, rx = (wm & 1) * 32;
    for (int it = 0; it < 9; it++) {
        if ((it & 1) == 0) {       // sync every 2 iterations
            CP_WAIT(0);
            __syncthreads();
        }
        if (it < 7) {
            const char* wb = (const char*)g_wb2 + (size_t)((it + 2) * 4 + g) * 10240;
            uint32_t Bb = sb + 33792u + (uint32_t)((it + 2) & 3) * 10240u;
#pragma unroll
            for (int ii = 0; ii < 5; ii++) {
                int lin = tid + ii * 128;
                CP16(Bb + lin * 16, wb + lin * 16, 16);
            }
        }
        CP_COMMIT();

        uint32_t Bb = sb + 33792u + (uint32_t)(it & 3) * 10240u;
        int ky = it / 3, kx = it - ky * 3;
        int aib = (ry + ky) * 66 + kx + rx + a_rl;
#pragma unroll
        for (int ks = 0; ks < 3; ks++) {   // ks=3 is all zeros (padded channels) -> skipped
            uint32_t a[2][4];
#pragma unroll
            for (int mt = 0; mt < 2; mt++) {
                int idx = aib + mt * 16;
                uint32_t ad = sb + (uint32_t)(idx * 128 + ((((ks << 1) + a_kh) ^ (idx & 7)) << 4));
                LDSM4(a[mt][0], a[mt][1], a[mt][2], a[mt][3], ad);
            }
#pragma unroll
            for (int p = 0; p < 5; p++) {
                int row = p * 16 + b_nl;
                uint32_t bd = Bb + (uint32_t)(row * 128 + ((((ks << 1) + b_kh) ^ (row & 7)) << 4));
                uint32_t b0, b1, b2, b3;
                LDSM4(b0, b1, b2, b3, bd);
#pragma unroll
                for (int mt = 0; mt < 2; mt++) {
                    MMA(acc[mt][p * 2],     a[mt], b0, b1);
                    MMA(acc[mt][p * 2 + 1], a[mt], b2, b3);
                }
            }
        }
    }
    // epilogue: NCHW stores into x2 slice (8-consecutive-row fragments = full sectors)
    float* ob = out + ((size_t)n * 512 + 192 + (size_t)g * 80) * HW + (size_t)y0 * 64;
    int r0 = wm * 32 + (l >> 2), c0 = (l & 3) * 2;
#pragma unroll
    for (int mt = 0; mt < 2; mt++)
#pragma unroll
        for (int nt = 0; nt < 10; nt++) {
            float* d = acc[mt][nt];
            int row = r0 + mt * 16, col = c0 + nt * 8;
            ob[(size_t)col * HW + row]           = d[0];
            ob[(size_t)(col + 1) * HW + row]     = d[1];
            ob[(size_t)col * HW + row + 8]       = d[2];
            ob[(size_t)(col + 1) * HW + row + 8] = d[3];
        }
}

// ---------------- launch ----------------
extern "C" void kernel_launch(void* const* d_in, const int* in_sizes, int n_in,
                              void* d_out, int out_size) {
    const float* x     = (const float*)d_in[0];
    const float* w1    = (const float*)d_in[1];
    const float* gamma = (const float*)d_in[2];
    const float* beta  = (const float*)d_in[3];
    const float* w2    = (const float*)d_in[4];
    float* out = (float*)d_out;

    cudaFuncSetAttribute(conv1_kernel, cudaFuncAttributeMaxDynamicSharedMemorySize, C1_SMEM);
    cudaFuncSetAttribute(conv2_kernel, cudaFuncAttributeMaxDynamicSharedMemorySize, C2_SMEM);

    lif_kernel  <<<dim3(16, 4, 8), 256>>>(x);
    prep1_kernel<<<1728, 256>>>(w1);
    prep2_kernel<<<720, 256>>>(w2);

    conv1_kernel<<<1024, 256, C1_SMEM>>>();   // writes g_y (fp16) + BN partials

    bn_final_kernel<<<192, 64>>>(gamma, beta);
    bn_apply_kernel<<<dim3(128, 32), 256>>>(out);

    conv2_kernel<<<4096, 128, C2_SMEM>>>(out);
}